// round 7
// baseline (speedup 1.0000x reference)
#include <cuda_runtime.h>
#include <math.h>
#include <stdint.h>

#define SQ    2048
#define DIM   2048
#define NH    16
#define HD    128
#define BATCH 2
#define NROWS 4096      // B*S
#define DLCA  4096
#define DFF   8192

// ---------------- scratch (static device globals; no allocs allowed) -------
__device__ float g_hn  [(size_t)NROWS*DIM];
__device__ float g_q   [(size_t)NROWS*DIM];
__device__ float g_k   [(size_t)NROWS*DIM];
__device__ float g_v   [(size_t)NROWS*DIM];
__device__ float g_attn[(size_t)NROWS*DIM];
__device__ float g_ao  [(size_t)NROWS*DIM];
__device__ float g_h   [(size_t)NROWS*DIM];
__device__ float g_t1  [(size_t)NROWS*DIM];
__device__ float g_b   [(size_t)NROWS*DLCA];
__device__ float g_u   [(size_t)NROWS*DLCA];
__device__ float g_a   [(size_t)NROWS*DLCA];
__device__ float g_gate[(size_t)NROWS*DFF];
__device__ float g_up  [(size_t)NROWS*DFF];
__device__ float g_diag[DLCA];
// tf32-rounded, K-major ([N][K]) weight copies
__device__ float g_wqkvT[(size_t)(3*DIM)*DIM];   // [6144][2048]  q|k|v stacked
__device__ float g_woT  [(size_t)DIM*DIM];
__device__ float g_wlT  [(size_t)DLCA*DIM];      // W_lca^T  [4096][2048]
__device__ float g_wl   [(size_t)DIM*DLCA];      // W_lca    [2048][4096] (rounded)
__device__ float g_wguT [(size_t)(2*DFF)*DIM];   // [16384][2048] gate|up stacked
__device__ float g_wdT  [(size_t)DIM*DFF];

// ---------------- tf32 helpers ---------------------------------------------
__device__ __forceinline__ unsigned f2tf32(float f) {
    unsigned r;
    asm("cvt.rna.tf32.f32 %0, %1;" : "=r"(r) : "f"(f));
    return r;
}
__device__ __forceinline__ float rtf32(float f) { return __uint_as_float(f2tf32(f)); }

#define CP_ASYNC16(dst, src) \
    asm volatile("cp.async.cg.shared.global [%0], [%1], 16;\n" :: "r"(dst), "l"(src))
#define CP_COMMIT() asm volatile("cp.async.commit_group;\n")
#define CP_WAIT1()  asm volatile("cp.async.wait_group 1;\n" ::: "memory")

#define MMA_TF32(c, a, b) \
    asm volatile("mma.sync.aligned.m16n8k8.row.col.f32.tf32.tf32.f32 " \
                 "{%0,%1,%2,%3}, {%4,%5,%6,%7}, {%8,%9}, {%0,%1,%2,%3};" \
                 : "+f"((c)[0]), "+f"((c)[1]), "+f"((c)[2]), "+f"((c)[3]) \
                 : "r"((a)[0]), "r"((a)[1]), "r"((a)[2]), "r"((a)[3]), \
                   "r"((b)[0]), "r"((b)[1]))

// ================= TF32 GEMM v3: fused epilogues ===========================
// C[4096,N] = A[4096,K] @ B[N,K]^T (B K-major). CTA 128x128, 4 warps (2x2),
// warp tile 64x64, BK=32, 3-stage cp.async, register-double-buffered frags.
// mode: 0=f32 store  1=rtf32 store  2=LCA init (C=b,p0=u,p1=a)
//       3=LCA update (p0=b,p1=u,p2=a,p3=diag; C unused)
//       4=residual add (C=acc+p0)  5=QKV split (C=q,p0=k,p1=v)
//       6=gate/up split (C=gate,p0=up)
#define GSTRIDE 36
#define AFL (128 * GSTRIDE)
#define GSTG (2 * AFL)
#define GEMM_SMEM_BYTES (3 * GSTG * 4)

#define LOADF(buf, ks) do { \
    _Pragma("unroll") \
    for (int mi = 0; mi < 4; ++mi) { \
        int r0 = wm * 64 + mi * 16 + g; \
        fa[buf][mi][0] = As[r0 * GSTRIDE + (ks) + q]; \
        fa[buf][mi][1] = As[(r0 + 8) * GSTRIDE + (ks) + q]; \
        fa[buf][mi][2] = As[r0 * GSTRIDE + (ks) + q + 4]; \
        fa[buf][mi][3] = As[(r0 + 8) * GSTRIDE + (ks) + q + 4]; \
    } \
    _Pragma("unroll") \
    for (int ni = 0; ni < 8; ++ni) { \
        int cn = wn * 64 + ni * 8 + g; \
        fb[buf][ni][0] = Bs[cn * GSTRIDE + (ks) + q]; \
        fb[buf][ni][1] = Bs[cn * GSTRIDE + (ks) + q + 4]; \
    } \
} while (0)

__global__ __launch_bounds__(128, 2) void gemm_tf32(
    const float* __restrict__ A, const float* __restrict__ B,
    float* __restrict__ C, float* __restrict__ p0, float* __restrict__ p1,
    float* __restrict__ p2, const float* __restrict__ p3,
    int N, int K, int mode)
{
    extern __shared__ float sm[];
    const int tid  = threadIdx.x;
    const int warp = tid >> 5, lane = tid & 31;
    const int wm = warp & 1, wn = warp >> 1;
    const int g = lane >> 2, q = lane & 3;
    const int bx = blockIdx.x, by = blockIdx.y;

    const size_t ar0 = (size_t)by * 128;
    const size_t br0 = (size_t)bx * 128;
    unsigned smB = (unsigned)__cvta_generic_to_shared(sm);

    float c[4][8][4];
#pragma unroll
    for (int i = 0; i < 4; ++i)
#pragma unroll
        for (int j = 0; j < 8; ++j)
#pragma unroll
            for (int r = 0; r < 4; ++r) c[i][j][r] = 0.f;

    const int T = K >> 5;

    auto load_stage = [&](int t, int s) {
        unsigned base = smB + (unsigned)(s * GSTG) * 4;
        const float* Ap = A + ar0 * K + (size_t)t * 32;
        const float* Bp = B + br0 * K + (size_t)t * 32;
#pragma unroll
        for (int i = 0; i < 8; ++i) {
            int u = tid + i * 128;
            int row = u >> 3, cc = (u & 7) << 2;
            CP_ASYNC16(base + (unsigned)(row * GSTRIDE + cc) * 4,
                       Ap + (size_t)row * K + cc);
            CP_ASYNC16(base + (unsigned)(AFL + row * GSTRIDE + cc) * 4,
                       Bp + (size_t)row * K + cc);
        }
    };

    load_stage(0, 0); CP_COMMIT();
    if (T > 1) load_stage(1, 1);
    CP_COMMIT();

    for (int t = 0; t < T; ++t) {
        CP_WAIT1();
        __syncthreads();
        if (t + 2 < T) load_stage(t + 2, (t + 2) % 3);
        CP_COMMIT();

        const unsigned* As = (const unsigned*)sm + (t % 3) * GSTG;
        const unsigned* Bs = As + AFL;

        unsigned fa[2][4][4], fb[2][8][2];
        LOADF(0, 0);
#pragma unroll
        for (int ks8 = 0; ks8 < 4; ++ks8) {
            const int cur = ks8 & 1;
            if (ks8 < 3) { LOADF(cur ^ 1, (ks8 + 1) * 8); }
#pragma unroll
            for (int mi = 0; mi < 4; ++mi)
#pragma unroll
                for (int ni = 0; ni < 8; ++ni)
                    MMA_TF32(c[mi][ni], fa[cur][mi], fb[cur][ni]);
        }
    }

    // ---------------- epilogue with fused ops ------------------------------
    // routing for split modes
    float* Cout = C;
    int Nout = N, colsub = 0;
    if (mode == 5) {
        int which = (int)(br0 >> 11);           // 0..2 per 2048 cols
        Cout = (which == 0) ? C : (which == 1 ? p0 : p1);
        Nout = 2048; colsub = which * 2048;
    } else if (mode == 6) {
        int which = (int)(br0 >> 13);           // 0..1 per 8192 cols
        Cout = which ? p0 : C;
        Nout = 8192; colsub = which * 8192;
    }

#pragma unroll
    for (int mi = 0; mi < 4; ++mi) {
        int row0 = (int)ar0 + wm * 64 + mi * 16 + g;
#pragma unroll
        for (int ni = 0; ni < 8; ++ni) {
            int col = (int)br0 + wn * 64 + ni * 8 + q * 2;
#pragma unroll
            for (int hh = 0; hh < 2; ++hh) {
                int r = row0 + hh * 8;
                float v0 = c[mi][ni][hh * 2 + 0];
                float v1 = c[mi][ni][hh * 2 + 1];
                if (mode == 0) {
                    *(float2*)(C + (size_t)r * N + col) = make_float2(v0, v1);
                } else if (mode == 1) {
                    *(float2*)(C + (size_t)r * N + col) =
                        make_float2(rtf32(v0), rtf32(v1));
                } else if (mode == 2) {
                    size_t i0 = (size_t)r * N + col;
                    *(float2*)(C + i0) = make_float2(v0, v1);        // b
                    float u0 = 0.1f * v0, u1 = 0.1f * v1;
                    *(float2*)(p0 + i0) = make_float2(u0, u1);       // u
                    *(float2*)(p1 + i0) = make_float2(                // a
                        rtf32(fmaxf(u0 - 0.1f, 0.f)),
                        rtf32(fmaxf(u1 - 0.1f, 0.f)));
                } else if (mode == 3) {
                    size_t i0 = (size_t)r * N + col;
                    float2 dg = *(const float2*)(p3 + col);
                    float2 av = *(const float2*)(p2 + i0);
                    float2 bb = *(const float2*)(p0 + i0);
                    float2 uv = *(const float2*)(p1 + i0);
                    float inh0 = v0 - av.x * dg.x;
                    float inh1 = v1 - av.y * dg.y;
                    uv.x += 0.1f * (bb.x - inh0 - uv.x);
                    uv.y += 0.1f * (bb.y - inh1 - uv.y);
                    *(float2*)(p1 + i0) = uv;
                    *(float2*)(p2 + i0) = make_float2(
                        rtf32(fmaxf(uv.x - 0.1f, 0.f)),
                        rtf32(fmaxf(uv.y - 0.1f, 0.f)));
                } else if (mode == 4) {
                    size_t i0 = (size_t)r * N + col;
                    float2 rv = *(const float2*)(p0 + i0);
                    *(float2*)(C + i0) = make_float2(v0 + rv.x, v1 + rv.y);
                } else {  // 5 / 6 routed plain f32
                    *(float2*)(Cout + (size_t)r * Nout + (col - colsub)) =
                        make_float2(v0, v1);
                }
            }
        }
    }
}

// ---------------- weight prep ----------------------------------------------
// W[K,N] f32 -> T[N][K] tf32-rounded f32
__global__ void transpose_round_kernel(const float* __restrict__ W,
                                       float* __restrict__ To, int K, int N)
{
    __shared__ float tsm[32][33];
    int n0 = blockIdx.x * 32, k0 = blockIdx.y * 32;
    int tx = threadIdx.x, ty = threadIdx.y;   // 32 x 8
#pragma unroll
    for (int i = 0; i < 4; ++i)
        tsm[ty + i * 8][tx] = W[(size_t)(k0 + ty + i * 8) * N + n0 + tx];
    __syncthreads();
#pragma unroll
    for (int i = 0; i < 4; ++i) {
        int n = n0 + ty + i * 8;
        To[(size_t)n * K + k0 + tx] = rtf32(tsm[tx][ty + i * 8]);
    }
}

__global__ void round_tf32_kernel(const float* __restrict__ s, float* __restrict__ d, int n4)
{
    int i = blockIdx.x * blockDim.x + threadIdx.x;
    if (i < n4) {
        float4 v = *(const float4*)(s + (size_t)i * 4);
        v.x = rtf32(v.x); v.y = rtf32(v.y); v.z = rtf32(v.z); v.w = rtf32(v.w);
        *(float4*)(d + (size_t)i * 4) = v;
    }
}

// ---------------- RMSNorm (tf32-rounded output) -----------------------------
__global__ __launch_bounds__(256) void rmsnorm_kernel(
    const float* __restrict__ x, const float* __restrict__ res,
    float* __restrict__ hsum, const float* __restrict__ w, float* __restrict__ out)
{
    __shared__ float red[8];
    int row = blockIdx.x, tid = threadIdx.x;
    const float* xr = x + (size_t)row * DIM;
    float4 v[2];
    float ss = 0.f;
#pragma unroll
    for (int p = 0; p < 2; ++p) {
        int cix = p * 1024 + tid * 4;
        v[p] = *(const float4*)(xr + cix);
        if (res) {
            float4 rv = *(const float4*)(res + (size_t)row * DIM + cix);
            v[p].x += rv.x; v[p].y += rv.y; v[p].z += rv.z; v[p].w += rv.w;
            *(float4*)(hsum + (size_t)row * DIM + cix) = v[p];
        }
        ss += v[p].x * v[p].x + v[p].y * v[p].y + v[p].z * v[p].z + v[p].w * v[p].w;
    }
#pragma unroll
    for (int off = 16; off; off >>= 1) ss += __shfl_xor_sync(~0u, ss, off);
    if ((tid & 31) == 0) red[tid >> 5] = ss;
    __syncthreads();
    if (tid == 0) {
        float t = 0.f;
#pragma unroll
        for (int i = 0; i < 8; ++i) t += red[i];
        red[0] = rsqrtf(t / (float)DIM + 1e-6f);
    }
    __syncthreads();
    float inv = red[0];
    float* orow = out + (size_t)row * DIM;
#pragma unroll
    for (int p = 0; p < 2; ++p) {
        int cix = p * 1024 + tid * 4;
        float4 wv = *(const float4*)(w + cix);
        float4 o;
        o.x = rtf32(v[p].x * inv * wv.x); o.y = rtf32(v[p].y * inv * wv.y);
        o.z = rtf32(v[p].z * inv * wv.z); o.w = rtf32(v[p].w * inv * wv.w);
        *(float4*)(orow + cix) = o;
    }
}

// ---------------- RoPE (in-place on q and k) --------------------------------
__global__ void rope_kernel(float* __restrict__ q, float* __restrict__ k)
{
    int idx = blockIdx.x * blockDim.x + threadIdx.x;
    if (idx >= NROWS * NH * 64) return;
    int i   = idx & 63;
    int h   = (idx >> 6) & (NH - 1);
    int row = idx >> 10;
    int pos = row & (SQ - 1);
    float inv = (float)exp(-((double)(2 * i) / (double)HD) * 9.210340371976184);
    float ang = (float)pos * inv;
    float sn, cs;
    sincosf(ang, &sn, &cs);
    size_t base = (size_t)row * DIM + (size_t)h * HD;
    float a = q[base + i], b = q[base + i + 64];
    q[base + i]      = a * cs - b * sn;
    q[base + i + 64] = b * cs + a * sn;
    a = k[base + i]; b = k[base + i + 64];
    k[base + i]      = a * cs - b * sn;
    k[base + i + 64] = b * cs + a * sn;
}

// ---------------- Flash attention (causal), 64x64 tiles ---------------------
#define ATTN_SMEM_FLOATS (64*128 + 64*132 + 64*128 + 64*64)
#define ATTN_SMEM_BYTES  (ATTN_SMEM_FLOATS * 4)

__global__ __launch_bounds__(256) void attn_kernel(
    const float* __restrict__ Q, const float* __restrict__ K,
    const float* __restrict__ V, float* __restrict__ O)
{
    extern __shared__ float smf[];
    float* Qs = smf;
    float* Ks = smf + 8192;
    float* Vs = smf + 8192 + 8448;
    float* Ps = smf + 8192 + 8448 + 8192;

    int qt = blockIdx.x, h = blockIdx.y, b = blockIdx.z;
    int tid = threadIdx.x;
    int ty = tid >> 4, tx = tid & 15;
    int qr0 = ty * 4;
    int dc0 = tx * 8;

    const float* Qb = Q + (size_t)b * SQ * DIM + (size_t)h * HD;
    const float* Kb = K + (size_t)b * SQ * DIM + (size_t)h * HD;
    const float* Vb = V + (size_t)b * SQ * DIM + (size_t)h * HD;

    for (int i = tid; i < 64 * 32; i += 256) {
        int r = i >> 5, cix = (i & 31) << 2;
        *(float4*)&Qs[r * 128 + cix] =
            *(const float4*)(Qb + (size_t)(qt * 64 + r) * DIM + cix);
    }

    float m[4], l[4], o[4][8];
#pragma unroll
    for (int i = 0; i < 4; ++i) {
        m[i] = -3.0e38f; l[i] = 0.f;
#pragma unroll
        for (int d = 0; d < 8; ++d) o[i][d] = 0.f;
    }
    __syncthreads();

    const float SCALE = 0.08838834764831845f;

    for (int kt = 0; kt <= qt; ++kt) {
        for (int i = tid; i < 64 * 32; i += 256) {
            int r = i >> 5, cix = (i & 31) << 2;
            *(float4*)&Ks[r * 132 + cix] =
                *(const float4*)(Kb + (size_t)(kt * 64 + r) * DIM + cix);
            *(float4*)&Vs[r * 128 + cix] =
                *(const float4*)(Vb + (size_t)(kt * 64 + r) * DIM + cix);
        }
        __syncthreads();

        float s[4][4];
#pragma unroll
        for (int i = 0; i < 4; ++i)
#pragma unroll
            for (int j = 0; j < 4; ++j) s[i][j] = 0.f;

        for (int d0 = 0; d0 < HD; d0 += 4) {
            float4 kf[4];
#pragma unroll
            for (int j = 0; j < 4; ++j)
                kf[j] = *(const float4*)&Ks[(tx + 16 * j) * 132 + d0];
#pragma unroll
            for (int i = 0; i < 4; ++i) {
                float4 qf = *(const float4*)&Qs[(qr0 + i) * 128 + d0];
#pragma unroll
                for (int j = 0; j < 4; ++j) {
                    s[i][j] = fmaf(qf.x, kf[j].x, s[i][j]);
                    s[i][j] = fmaf(qf.y, kf[j].y, s[i][j]);
                    s[i][j] = fmaf(qf.z, kf[j].z, s[i][j]);
                    s[i][j] = fmaf(qf.w, kf[j].w, s[i][j]);
                }
            }
        }

#pragma unroll
        for (int i = 0; i < 4; ++i)
#pragma unroll
            for (int j = 0; j < 4; ++j) s[i][j] *= SCALE;

        if (kt == qt) {
#pragma unroll
            for (int i = 0; i < 4; ++i) {
                int qidx = qt * 64 + qr0 + i;
#pragma unroll
                for (int j = 0; j < 4; ++j) {
                    int kidx = kt * 64 + tx + 16 * j;
                    if (kidx > qidx) s[i][j] = -1e30f;
                }
            }
        }

#pragma unroll
        for (int i = 0; i < 4; ++i) {
            float mr = fmaxf(fmaxf(s[i][0], s[i][1]), fmaxf(s[i][2], s[i][3]));
#pragma unroll
            for (int off = 1; off < 16; off <<= 1)
                mr = fmaxf(mr, __shfl_xor_sync(~0u, mr, off));
            float mn = fmaxf(m[i], mr);
            float corr = __expf(m[i] - mn);
            m[i] = mn;
            float p0 = __expf(s[i][0] - mn);
            float p1 = __expf(s[i][1] - mn);
            float p2 = __expf(s[i][2] - mn);
            float p3 = __expf(s[i][3] - mn);
            float ls = p0 + p1 + p2 + p3;
#pragma unroll
            for (int off = 1; off < 16; off <<= 1)
                ls += __shfl_xor_sync(~0u, ls, off);
            l[i] = l[i] * corr + ls;
#pragma unroll
            for (int d = 0; d < 8; ++d) o[i][d] *= corr;
            Ps[(qr0 + i) * 64 + tx]      = p0;
            Ps[(qr0 + i) * 64 + tx + 16] = p1;
            Ps[(qr0 + i) * 64 + tx + 32] = p2;
            Ps[(qr0 + i) * 64 + tx + 48] = p3;
        }
        __syncthreads();

        for (int kk = 0; kk < 64; ++kk) {
            float4 v0 = *(const float4*)&Vs[kk * 128 + dc0];
            float4 v1 = *(const float4*)&Vs[kk * 128 + dc0 + 4];
#pragma unroll
            for (int i = 0; i < 4; ++i) {
                float p = Ps[(qr0 + i) * 64 + kk];
                o[i][0] = fmaf(p, v0.x, o[i][0]);
                o[i][1] = fmaf(p, v0.y, o[i][1]);
                o[i][2] = fmaf(p, v0.z, o[i][2]);
                o[i][3] = fmaf(p, v0.w, o[i][3]);
                o[i][4] = fmaf(p, v1.x, o[i][4]);
                o[i][5] = fmaf(p, v1.y, o[i][5]);
                o[i][6] = fmaf(p, v1.z, o[i][6]);
                o[i][7] = fmaf(p, v1.w, o[i][7]);
            }
        }
        __syncthreads();
    }

    // tf32-rounded output (feeds Wo GEMM)
#pragma unroll
    for (int i = 0; i < 4; ++i) {
        float inv = 1.f / l[i];
        int row = qt * 64 + qr0 + i;
        float* op = O + (size_t)(b * SQ + row) * DIM + (size_t)h * HD + dc0;
        float4 r0 = make_float4(rtf32(o[i][0] * inv), rtf32(o[i][1] * inv),
                                rtf32(o[i][2] * inv), rtf32(o[i][3] * inv));
        float4 r1 = make_float4(rtf32(o[i][4] * inv), rtf32(o[i][5] * inv),
                                rtf32(o[i][6] * inv), rtf32(o[i][7] * inv));
        *(float4*)op       = r0;
        *(float4*)(op + 4) = r1;
    }
}

// ---------------- elementwise ----------------------------------------------
__global__ void diagG_kernel(const float* __restrict__ W, float* __restrict__ diag)
{
    int j = blockIdx.x * blockDim.x + threadIdx.x;
    if (j < DLCA) {
        float s = 0.f;
        for (int i = 0; i < DIM; ++i) {
            float w = W[(size_t)i * DLCA + j];
            s = fmaf(w, w, s);
        }
        diag[j] = s;
    }
}

__global__ void silu_mul_kernel(float* __restrict__ gte, const float* __restrict__ up, int n)
{
    int i = blockIdx.x * blockDim.x + threadIdx.x;
    if (i < n) {
        float x = gte[i];
        float sig = 1.f / (1.f + expf(-x));
        gte[i] = rtf32(x * sig * up[i]);
    }
}

// ---------------- launch ----------------------------------------------------
extern "C" void kernel_launch(void* const* d_in, const int* in_sizes, int n_in,
                              void* d_out, int out_size)
{
    const float* x       = (const float*)d_in[0];
    const float* w_in    = (const float*)d_in[1];
    const float* w_lcaN  = (const float*)d_in[2];
    const float* w_post  = (const float*)d_in[3];
    const float* Wq      = (const float*)d_in[4];
    const float* Wk      = (const float*)d_in[5];
    const float* Wv      = (const float*)d_in[6];
    const float* Wo      = (const float*)d_in[7];
    const float* W_lca   = (const float*)d_in[8];
    const float* W_gate  = (const float*)d_in[9];
    const float* W_up    = (const float*)d_in[10];
    const float* W_down  = (const float*)d_in[11];
    float* out = (float*)d_out;

    float *hn, *q, *k, *v, *attn, *ao, *h, *t1, *b, *u, *a, *gate, *up, *diag;
    float *wqkvT, *woT, *wlT, *wl, *wguT, *wdT;
    cudaGetSymbolAddress((void**)&hn,   g_hn);
    cudaGetSymbolAddress((void**)&q,    g_q);
    cudaGetSymbolAddress((void**)&k,    g_k);
    cudaGetSymbolAddress((void**)&v,    g_v);
    cudaGetSymbolAddress((void**)&attn, g_attn);
    cudaGetSymbolAddress((void**)&ao,   g_ao);
    cudaGetSymbolAddress((void**)&h,    g_h);
    cudaGetSymbolAddress((void**)&t1,   g_t1);
    cudaGetSymbolAddress((void**)&b,    g_b);
    cudaGetSymbolAddress((void**)&u,    g_u);
    cudaGetSymbolAddress((void**)&a,    g_a);
    cudaGetSymbolAddress((void**)&gate, g_gate);
    cudaGetSymbolAddress((void**)&up,   g_up);
    cudaGetSymbolAddress((void**)&diag, g_diag);
    cudaGetSymbolAddress((void**)&wqkvT, g_wqkvT);
    cudaGetSymbolAddress((void**)&woT,   g_woT);
    cudaGetSymbolAddress((void**)&wlT,   g_wlT);
    cudaGetSymbolAddress((void**)&wl,    g_wl);
    cudaGetSymbolAddress((void**)&wguT,  g_wguT);
    cudaGetSymbolAddress((void**)&wdT,   g_wdT);

    cudaFuncSetAttribute(attn_kernel,
                         cudaFuncAttributeMaxDynamicSharedMemorySize, ATTN_SMEM_BYTES);
    cudaFuncSetAttribute(gemm_tf32,
                         cudaFuncAttributeMaxDynamicSharedMemorySize, GEMM_SMEM_BYTES);

    const int NF = NROWS * DFF;
    dim3 tp(32, 8);

    // ---- weight prep: transpose + tf32 round (K-major [N][K]) ----
    transpose_round_kernel<<<dim3(DIM/32,  DIM/32), tp>>>(Wq, wqkvT,                          DIM, DIM);
    transpose_round_kernel<<<dim3(DIM/32,  DIM/32), tp>>>(Wk, wqkvT + (size_t)DIM*DIM,        DIM, DIM);
    transpose_round_kernel<<<dim3(DIM/32,  DIM/32), tp>>>(Wv, wqkvT + (size_t)2*DIM*DIM,      DIM, DIM);
    transpose_round_kernel<<<dim3(DIM/32,  DIM/32), tp>>>(Wo, woT, DIM, DIM);
    transpose_round_kernel<<<dim3(DLCA/32, DIM/32), tp>>>(W_lca, wlT, DIM, DLCA);
    round_tf32_kernel<<<(DIM*DLCA/4 + 255)/256, 256>>>(W_lca, wl, DIM*DLCA/4);
    transpose_round_kernel<<<dim3(DFF/32,  DIM/32), tp>>>(W_gate, wguT,                       DIM, DFF);
    transpose_round_kernel<<<dim3(DFF/32,  DIM/32), tp>>>(W_up,   wguT + (size_t)DFF*DIM,     DIM, DFF);
    transpose_round_kernel<<<dim3(DIM/32,  DFF/32), tp>>>(W_down, wdT, DFF, DIM);
    diagG_kernel<<<DLCA / 256, 256>>>(W_lca, diag);

    dim3 gQKV(3*DIM / 128, NROWS / 128);  // (48, 32)
    dim3 gD  (DIM / 128,   NROWS / 128);  // (16, 32)
    dim3 gL  (DLCA / 128,  NROWS / 128);  // (32, 32)
    dim3 gGU (2*DFF / 128, NROWS / 128);  // (128, 32)

    // ---- attention block ----
    rmsnorm_kernel<<<NROWS, 256>>>(x, nullptr, nullptr, w_in, hn);
    gemm_tf32<<<gQKV, 128, GEMM_SMEM_BYTES>>>(hn, wqkvT, q, k, v, nullptr, nullptr,
                                              3*DIM, DIM, 5);
    rope_kernel<<<(NROWS * NH * 64 + 255) / 256, 256>>>(q, k);
    attn_kernel<<<dim3(SQ / 64, NH, BATCH), 256, ATTN_SMEM_BYTES>>>(q, k, v, attn);
    gemm_tf32<<<gD, 128, GEMM_SMEM_BYTES>>>(attn, woT, ao, nullptr, nullptr, nullptr, nullptr,
                                            DIM, DIM, 0);

    // ---- LCA block ----  (h = x + ao fused into rmsnorm; init in epilogue)
    rmsnorm_kernel<<<NROWS, 256>>>(x, ao, h, w_lcaN, hn);
    gemm_tf32<<<gL, 128, GEMM_SMEM_BYTES>>>(hn, wlT, b, u, a, nullptr, nullptr,
                                            DLCA, DIM, 2);
    for (int it = 0; it < 9; ++it) {
        gemm_tf32<<<gD, 128, GEMM_SMEM_BYTES>>>(a, wl, t1, nullptr, nullptr, nullptr, nullptr,
                                                DIM, DLCA, 1);
        gemm_tf32<<<gL, 128, GEMM_SMEM_BYTES>>>(t1, wlT, u, b, u, a, diag,
                                                DLCA, DIM, 3);
    }
    gemm_tf32<<<gD, 128, GEMM_SMEM_BYTES>>>(a, wl, h, nullptr, nullptr, nullptr, nullptr,
                                            DIM, DLCA, 0);

    // ---- MLP block ----
    rmsnorm_kernel<<<NROWS, 256>>>(h, nullptr, nullptr, w_post, hn);
    gemm_tf32<<<gGU, 128, GEMM_SMEM_BYTES>>>(hn, wguT, gate, up, nullptr, nullptr, nullptr,
                                             2*DFF, DIM, 6);
    silu_mul_kernel<<<(NF + 255) / 256, 256>>>(gate, up, NF);
    gemm_tf32<<<gD, 128, GEMM_SMEM_BYTES>>>(gate, wdT, out, h, nullptr, nullptr, nullptr,
                                            DIM, DFF, 4);
}

// round 8
// speedup vs baseline: 1.5389x; 1.5389x over previous
#include <cuda_runtime.h>
#include <math.h>
#include <stdint.h>

#define SQ    2048
#define DIM   2048
#define NH    16
#define HD    128
#define BATCH 2
#define NROWS 4096      // B*S
#define DLCA  4096
#define DFF   8192

// ---------------- scratch (static device globals; no allocs allowed) -------
__device__ float g_hn  [(size_t)NROWS*DIM];
__device__ float g_q   [(size_t)NROWS*DIM];
__device__ float g_k   [(size_t)NROWS*DIM];
__device__ float g_v   [(size_t)NROWS*DIM];
__device__ float g_attn[(size_t)NROWS*DIM];
__device__ float g_ao  [(size_t)NROWS*DIM];
__device__ float g_h   [(size_t)NROWS*DIM];
__device__ float g_t1  [(size_t)NROWS*DIM];
__device__ float g_b   [(size_t)NROWS*DLCA];
__device__ float g_u   [(size_t)NROWS*DLCA];
__device__ float g_a   [(size_t)NROWS*DLCA];
__device__ float g_gate[(size_t)NROWS*DFF];
__device__ float g_up  [(size_t)NROWS*DFF];
__device__ float g_diag[DLCA];
// tf32-rounded, K-major ([N][K]) weight copies
__device__ float g_wqkvT[(size_t)(3*DIM)*DIM];   // [6144][2048]  q|k|v stacked
__device__ float g_woT  [(size_t)DIM*DIM];
__device__ float g_wlT  [(size_t)DLCA*DIM];      // W_lca^T  [4096][2048]
__device__ float g_wl   [(size_t)DIM*DLCA];      // W_lca    [2048][4096] (rounded)
__device__ float g_wguT [(size_t)(2*DFF)*DIM];   // [16384][2048] gate|up stacked
__device__ float g_wdT  [(size_t)DIM*DFF];

// ---------------- tf32 helpers ---------------------------------------------
__device__ __forceinline__ unsigned f2tf32(float f) {
    unsigned r;
    asm("cvt.rna.tf32.f32 %0, %1;" : "=r"(r) : "f"(f));
    return r;
}
__device__ __forceinline__ float rtf32(float f) { return __uint_as_float(f2tf32(f)); }

#define CP_ASYNC16(dst, src) \
    asm volatile("cp.async.cg.shared.global [%0], [%1], 16;\n" :: "r"(dst), "l"(src))
#define CP_COMMIT() asm volatile("cp.async.commit_group;\n")
#define CP_WAIT1()  asm volatile("cp.async.wait_group 1;\n" ::: "memory")

#define MMA_TF32(c, a, b) \
    asm volatile("mma.sync.aligned.m16n8k8.row.col.f32.tf32.tf32.f32 " \
                 "{%0,%1,%2,%3}, {%4,%5,%6,%7}, {%8,%9}, {%0,%1,%2,%3};" \
                 : "+f"((c)[0]), "+f"((c)[1]), "+f"((c)[2]), "+f"((c)[3]) \
                 : "r"((a)[0]), "r"((a)[1]), "r"((a)[2]), "r"((a)[3]), \
                   "r"((b)[0]), "r"((b)[1]))

// ================= TF32 GEMM (R5 mainloop + templated fused epilogues) =====
// C[4096,N] = A[4096,K] @ B[N,K]^T (B K-major). CTA 128x128, 4 warps (2x2),
// warp tile 64x64, BK=32, 3-stage cp.async, single sync per tile.
// MODE: 0=f32 store  1=rtf32 store  2=LCA init (C=b,p0=u,p1=a)
//       3=LCA update (p0=b,p1=u,p2=a,p3=diag)  4=residual add (C=acc+p0)
//       5=QKV split (C=q,p0=k,p1=v)            6=gate/up split (C=gate,p0=up)
#define GSTRIDE 36
#define AFL (128 * GSTRIDE)
#define GSTG (2 * AFL)
#define GEMM_SMEM_BYTES (3 * GSTG * 4)

template<int MODE>
__global__ __launch_bounds__(128, 2) void gemm_tf32(
    const float* __restrict__ A, const float* __restrict__ B,
    float* __restrict__ C, float* __restrict__ p0, float* __restrict__ p1,
    float* __restrict__ p2, const float* __restrict__ p3,
    int N, int K)
{
    extern __shared__ float sm[];
    const int tid  = threadIdx.x;
    const int warp = tid >> 5, lane = tid & 31;
    const int wm = warp & 1, wn = warp >> 1;
    const int g = lane >> 2, q = lane & 3;
    const int bx = blockIdx.x, by = blockIdx.y;

    const size_t ar0 = (size_t)by * 128;
    const size_t br0 = (size_t)bx * 128;
    unsigned smB = (unsigned)__cvta_generic_to_shared(sm);

    float c[4][8][4];
#pragma unroll
    for (int i = 0; i < 4; ++i)
#pragma unroll
        for (int j = 0; j < 8; ++j)
#pragma unroll
            for (int r = 0; r < 4; ++r) c[i][j][r] = 0.f;

    const int T = K >> 5;

    auto load_stage = [&](int t, int s) {
        unsigned base = smB + (unsigned)(s * GSTG) * 4;
        const float* Ap = A + ar0 * K + (size_t)t * 32;
        const float* Bp = B + br0 * K + (size_t)t * 32;
#pragma unroll
        for (int i = 0; i < 8; ++i) {
            int u = tid + i * 128;
            int row = u >> 3, cc = (u & 7) << 2;
            CP_ASYNC16(base + (unsigned)(row * GSTRIDE + cc) * 4,
                       Ap + (size_t)row * K + cc);
            CP_ASYNC16(base + (unsigned)(AFL + row * GSTRIDE + cc) * 4,
                       Bp + (size_t)row * K + cc);
        }
    };

    load_stage(0, 0); CP_COMMIT();
    if (T > 1) load_stage(1, 1);
    CP_COMMIT();

    for (int t = 0; t < T; ++t) {
        CP_WAIT1();
        __syncthreads();
        if (t + 2 < T) load_stage(t + 2, (t + 2) % 3);
        CP_COMMIT();

        const unsigned* As = (const unsigned*)sm + (t % 3) * GSTG;
        const unsigned* Bs = As + AFL;

#pragma unroll
        for (int ks8 = 0; ks8 < 4; ++ks8) {
            const int ks = ks8 * 8;
            unsigned a[4][4], b[8][2];
#pragma unroll
            for (int mi = 0; mi < 4; ++mi) {
                int r0 = wm * 64 + mi * 16 + g;
                a[mi][0] = As[r0 * GSTRIDE + ks + q];
                a[mi][1] = As[(r0 + 8) * GSTRIDE + ks + q];
                a[mi][2] = As[r0 * GSTRIDE + ks + q + 4];
                a[mi][3] = As[(r0 + 8) * GSTRIDE + ks + q + 4];
            }
#pragma unroll
            for (int ni = 0; ni < 8; ++ni) {
                int cn = wn * 64 + ni * 8 + g;
                b[ni][0] = Bs[cn * GSTRIDE + ks + q];
                b[ni][1] = Bs[cn * GSTRIDE + ks + q + 4];
            }
#pragma unroll
            for (int mi = 0; mi < 4; ++mi)
#pragma unroll
                for (int ni = 0; ni < 8; ++ni)
                    MMA_TF32(c[mi][ni], a[mi], b[ni]);
        }
    }

    // ---------------- templated epilogue -----------------------------------
    float* Cout = C;
    int Nout = N, colsub = 0;
    if constexpr (MODE == 5) {
        int which = (int)(br0 >> 11);           // 0..2 per 2048 cols
        Cout = (which == 0) ? C : (which == 1 ? p0 : p1);
        Nout = 2048; colsub = which * 2048;
    }
    if constexpr (MODE == 6) {
        int which = (int)(br0 >> 13);           // 0..1 per 8192 cols
        Cout = which ? p0 : C;
        Nout = 8192; colsub = which * 8192;
    }

#pragma unroll
    for (int mi = 0; mi < 4; ++mi) {
        int row0 = (int)ar0 + wm * 64 + mi * 16 + g;
#pragma unroll
        for (int ni = 0; ni < 8; ++ni) {
            int col = (int)br0 + wn * 64 + ni * 8 + q * 2;
#pragma unroll
            for (int hh = 0; hh < 2; ++hh) {
                int r = row0 + hh * 8;
                float v0 = c[mi][ni][hh * 2 + 0];
                float v1 = c[mi][ni][hh * 2 + 1];
                if constexpr (MODE == 0) {
                    *(float2*)(C + (size_t)r * N + col) = make_float2(v0, v1);
                } else if constexpr (MODE == 1) {
                    *(float2*)(C + (size_t)r * N + col) =
                        make_float2(rtf32(v0), rtf32(v1));
                } else if constexpr (MODE == 2) {
                    size_t i0 = (size_t)r * N + col;
                    *(float2*)(C + i0) = make_float2(v0, v1);        // b
                    float u0 = 0.1f * v0, u1 = 0.1f * v1;
                    *(float2*)(p0 + i0) = make_float2(u0, u1);       // u
                    *(float2*)(p1 + i0) = make_float2(                // a
                        rtf32(fmaxf(u0 - 0.1f, 0.f)),
                        rtf32(fmaxf(u1 - 0.1f, 0.f)));
                } else if constexpr (MODE == 3) {
                    size_t i0 = (size_t)r * N + col;
                    float2 dg = *(const float2*)(p3 + col);
                    float2 av = *(const float2*)(p2 + i0);
                    float2 bb = *(const float2*)(p0 + i0);
                    float2 uv = *(const float2*)(p1 + i0);
                    float inh0 = v0 - av.x * dg.x;
                    float inh1 = v1 - av.y * dg.y;
                    uv.x += 0.1f * (bb.x - inh0 - uv.x);
                    uv.y += 0.1f * (bb.y - inh1 - uv.y);
                    *(float2*)(p1 + i0) = uv;
                    *(float2*)(p2 + i0) = make_float2(
                        rtf32(fmaxf(uv.x - 0.1f, 0.f)),
                        rtf32(fmaxf(uv.y - 0.1f, 0.f)));
                } else if constexpr (MODE == 4) {
                    size_t i0 = (size_t)r * N + col;
                    float2 rv = *(const float2*)(p0 + i0);
                    *(float2*)(C + i0) = make_float2(v0 + rv.x, v1 + rv.y);
                } else {  // 5 / 6
                    *(float2*)(Cout + (size_t)r * Nout + (col - colsub)) =
                        make_float2(v0, v1);
                }
            }
        }
    }
}

// ---------------- weight prep ----------------------------------------------
__global__ void transpose_round_kernel(const float* __restrict__ W,
                                       float* __restrict__ To, int K, int N)
{
    __shared__ float tsm[32][33];
    int n0 = blockIdx.x * 32, k0 = blockIdx.y * 32;
    int tx = threadIdx.x, ty = threadIdx.y;   // 32 x 8
#pragma unroll
    for (int i = 0; i < 4; ++i)
        tsm[ty + i * 8][tx] = W[(size_t)(k0 + ty + i * 8) * N + n0 + tx];
    __syncthreads();
#pragma unroll
    for (int i = 0; i < 4; ++i) {
        int n = n0 + ty + i * 8;
        To[(size_t)n * K + k0 + tx] = rtf32(tsm[tx][ty + i * 8]);
    }
}

__global__ void round_tf32_kernel(const float* __restrict__ s, float* __restrict__ d, int n4)
{
    int i = blockIdx.x * blockDim.x + threadIdx.x;
    if (i < n4) {
        float4 v = *(const float4*)(s + (size_t)i * 4);
        v.x = rtf32(v.x); v.y = rtf32(v.y); v.z = rtf32(v.z); v.w = rtf32(v.w);
        *(float4*)(d + (size_t)i * 4) = v;
    }
}

// ---------------- RMSNorm (tf32-rounded output) -----------------------------
__global__ __launch_bounds__(256) void rmsnorm_kernel(
    const float* __restrict__ x, const float* __restrict__ res,
    float* __restrict__ hsum, const float* __restrict__ w, float* __restrict__ out)
{
    __shared__ float red[8];
    int row = blockIdx.x, tid = threadIdx.x;
    const float* xr = x + (size_t)row * DIM;
    float4 v[2];
    float ss = 0.f;
#pragma unroll
    for (int p = 0; p < 2; ++p) {
        int cix = p * 1024 + tid * 4;
        v[p] = *(const float4*)(xr + cix);
        if (res) {
            float4 rv = *(const float4*)(res + (size_t)row * DIM + cix);
            v[p].x += rv.x; v[p].y += rv.y; v[p].z += rv.z; v[p].w += rv.w;
            *(float4*)(hsum + (size_t)row * DIM + cix) = v[p];
        }
        ss += v[p].x * v[p].x + v[p].y * v[p].y + v[p].z * v[p].z + v[p].w * v[p].w;
    }
#pragma unroll
    for (int off = 16; off; off >>= 1) ss += __shfl_xor_sync(~0u, ss, off);
    if ((tid & 31) == 0) red[tid >> 5] = ss;
    __syncthreads();
    if (tid == 0) {
        float t = 0.f;
#pragma unroll
        for (int i = 0; i < 8; ++i) t += red[i];
        red[0] = rsqrtf(t / (float)DIM + 1e-6f);
    }
    __syncthreads();
    float inv = red[0];
    float* orow = out + (size_t)row * DIM;
#pragma unroll
    for (int p = 0; p < 2; ++p) {
        int cix = p * 1024 + tid * 4;
        float4 wv = *(const float4*)(w + cix);
        float4 o;
        o.x = rtf32(v[p].x * inv * wv.x); o.y = rtf32(v[p].y * inv * wv.y);
        o.z = rtf32(v[p].z * inv * wv.z); o.w = rtf32(v[p].w * inv * wv.w);
        *(float4*)(orow + cix) = o;
    }
}

// ---------------- RoPE (in-place on q and k) --------------------------------
__global__ void rope_kernel(float* __restrict__ q, float* __restrict__ k)
{
    int idx = blockIdx.x * blockDim.x + threadIdx.x;
    if (idx >= NROWS * NH * 64) return;
    int i   = idx & 63;
    int h   = (idx >> 6) & (NH - 1);
    int row = idx >> 10;
    int pos = row & (SQ - 1);
    float inv = (float)exp(-((double)(2 * i) / (double)HD) * 9.210340371976184);
    float ang = (float)pos * inv;
    float sn, cs;
    sincosf(ang, &sn, &cs);
    size_t base = (size_t)row * DIM + (size_t)h * HD;
    float a = q[base + i], b = q[base + i + 64];
    q[base + i]      = a * cs - b * sn;
    q[base + i + 64] = b * cs + a * sn;
    a = k[base + i]; b = k[base + i + 64];
    k[base + i]      = a * cs - b * sn;
    k[base + i + 64] = b * cs + a * sn;
}

// ---------------- Flash attention (causal), 64x64 tiles ---------------------
#define ATTN_SMEM_FLOATS (64*128 + 64*132 + 64*128 + 64*64)
#define ATTN_SMEM_BYTES  (ATTN_SMEM_FLOATS * 4)

__global__ __launch_bounds__(256) void attn_kernel(
    const float* __restrict__ Q, const float* __restrict__ K,
    const float* __restrict__ V, float* __restrict__ O)
{
    extern __shared__ float smf[];
    float* Qs = smf;
    float* Ks = smf + 8192;
    float* Vs = smf + 8192 + 8448;
    float* Ps = smf + 8192 + 8448 + 8192;

    int qt = blockIdx.x, h = blockIdx.y, b = blockIdx.z;
    int tid = threadIdx.x;
    int ty = tid >> 4, tx = tid & 15;
    int qr0 = ty * 4;
    int dc0 = tx * 8;

    const float* Qb = Q + (size_t)b * SQ * DIM + (size_t)h * HD;
    const float* Kb = K + (size_t)b * SQ * DIM + (size_t)h * HD;
    const float* Vb = V + (size_t)b * SQ * DIM + (size_t)h * HD;

    for (int i = tid; i < 64 * 32; i += 256) {
        int r = i >> 5, cix = (i & 31) << 2;
        *(float4*)&Qs[r * 128 + cix] =
            *(const float4*)(Qb + (size_t)(qt * 64 + r) * DIM + cix);
    }

    float m[4], l[4], o[4][8];
#pragma unroll
    for (int i = 0; i < 4; ++i) {
        m[i] = -3.0e38f; l[i] = 0.f;
#pragma unroll
        for (int d = 0; d < 8; ++d) o[i][d] = 0.f;
    }
    __syncthreads();

    const float SCALE = 0.08838834764831845f;

    for (int kt = 0; kt <= qt; ++kt) {
        for (int i = tid; i < 64 * 32; i += 256) {
            int r = i >> 5, cix = (i & 31) << 2;
            *(float4*)&Ks[r * 132 + cix] =
                *(const float4*)(Kb + (size_t)(kt * 64 + r) * DIM + cix);
            *(float4*)&Vs[r * 128 + cix] =
                *(const float4*)(Vb + (size_t)(kt * 64 + r) * DIM + cix);
        }
        __syncthreads();

        float s[4][4];
#pragma unroll
        for (int i = 0; i < 4; ++i)
#pragma unroll
            for (int j = 0; j < 4; ++j) s[i][j] = 0.f;

        for (int d0 = 0; d0 < HD; d0 += 4) {
            float4 kf[4];
#pragma unroll
            for (int j = 0; j < 4; ++j)
                kf[j] = *(const float4*)&Ks[(tx + 16 * j) * 132 + d0];
#pragma unroll
            for (int i = 0; i < 4; ++i) {
                float4 qf = *(const float4*)&Qs[(qr0 + i) * 128 + d0];
#pragma unroll
                for (int j = 0; j < 4; ++j) {
                    s[i][j] = fmaf(qf.x, kf[j].x, s[i][j]);
                    s[i][j] = fmaf(qf.y, kf[j].y, s[i][j]);
                    s[i][j] = fmaf(qf.z, kf[j].z, s[i][j]);
                    s[i][j] = fmaf(qf.w, kf[j].w, s[i][j]);
                }
            }
        }

#pragma unroll
        for (int i = 0; i < 4; ++i)
#pragma unroll
            for (int j = 0; j < 4; ++j) s[i][j] *= SCALE;

        if (kt == qt) {
#pragma unroll
            for (int i = 0; i < 4; ++i) {
                int qidx = qt * 64 + qr0 + i;
#pragma unroll
                for (int j = 0; j < 4; ++j) {
                    int kidx = kt * 64 + tx + 16 * j;
                    if (kidx > qidx) s[i][j] = -1e30f;
                }
            }
        }

#pragma unroll
        for (int i = 0; i < 4; ++i) {
            float mr = fmaxf(fmaxf(s[i][0], s[i][1]), fmaxf(s[i][2], s[i][3]));
#pragma unroll
            for (int off = 1; off < 16; off <<= 1)
                mr = fmaxf(mr, __shfl_xor_sync(~0u, mr, off));
            float mn = fmaxf(m[i], mr);
            float corr = __expf(m[i] - mn);
            m[i] = mn;
            float p0 = __expf(s[i][0] - mn);
            float p1 = __expf(s[i][1] - mn);
            float p2 = __expf(s[i][2] - mn);
            float p3 = __expf(s[i][3] - mn);
            float ls = p0 + p1 + p2 + p3;
#pragma unroll
            for (int off = 1; off < 16; off <<= 1)
                ls += __shfl_xor_sync(~0u, ls, off);
            l[i] = l[i] * corr + ls;
#pragma unroll
            for (int d = 0; d < 8; ++d) o[i][d] *= corr;
            Ps[(qr0 + i) * 64 + tx]      = p0;
            Ps[(qr0 + i) * 64 + tx + 16] = p1;
            Ps[(qr0 + i) * 64 + tx + 32] = p2;
            Ps[(qr0 + i) * 64 + tx + 48] = p3;
        }
        __syncthreads();

        for (int kk = 0; kk < 64; ++kk) {
            float4 v0 = *(const float4*)&Vs[kk * 128 + dc0];
            float4 v1 = *(const float4*)&Vs[kk * 128 + dc0 + 4];
#pragma unroll
            for (int i = 0; i < 4; ++i) {
                float p = Ps[(qr0 + i) * 64 + kk];
                o[i][0] = fmaf(p, v0.x, o[i][0]);
                o[i][1] = fmaf(p, v0.y, o[i][1]);
                o[i][2] = fmaf(p, v0.z, o[i][2]);
                o[i][3] = fmaf(p, v0.w, o[i][3]);
                o[i][4] = fmaf(p, v1.x, o[i][4]);
                o[i][5] = fmaf(p, v1.y, o[i][5]);
                o[i][6] = fmaf(p, v1.z, o[i][6]);
                o[i][7] = fmaf(p, v1.w, o[i][7]);
            }
        }
        __syncthreads();
    }

    // tf32-rounded output (feeds Wo GEMM)
#pragma unroll
    for (int i = 0; i < 4; ++i) {
        float inv = 1.f / l[i];
        int row = qt * 64 + qr0 + i;
        float* op = O + (size_t)(b * SQ + row) * DIM + (size_t)h * HD + dc0;
        float4 r0 = make_float4(rtf32(o[i][0] * inv), rtf32(o[i][1] * inv),
                                rtf32(o[i][2] * inv), rtf32(o[i][3] * inv));
        float4 r1 = make_float4(rtf32(o[i][4] * inv), rtf32(o[i][5] * inv),
                                rtf32(o[i][6] * inv), rtf32(o[i][7] * inv));
        *(float4*)op       = r0;
        *(float4*)(op + 4) = r1;
    }
}

// ---------------- elementwise ----------------------------------------------
__global__ void diagG_kernel(const float* __restrict__ W, float* __restrict__ diag)
{
    int j = blockIdx.x * blockDim.x + threadIdx.x;
    if (j < DLCA) {
        float s = 0.f;
        for (int i = 0; i < DIM; ++i) {
            float w = W[(size_t)i * DLCA + j];
            s = fmaf(w, w, s);
        }
        diag[j] = s;
    }
}

__global__ void silu_mul_kernel(float* __restrict__ gte, const float* __restrict__ up, int n)
{
    int i = blockIdx.x * blockDim.x + threadIdx.x;
    if (i < n) {
        float x = gte[i];
        float sig = 1.f / (1.f + expf(-x));
        gte[i] = rtf32(x * sig * up[i]);
    }
}

// ---------------- launch ----------------------------------------------------
extern "C" void kernel_launch(void* const* d_in, const int* in_sizes, int n_in,
                              void* d_out, int out_size)
{
    const float* x       = (const float*)d_in[0];
    const float* w_in    = (const float*)d_in[1];
    const float* w_lcaN  = (const float*)d_in[2];
    const float* w_post  = (const float*)d_in[3];
    const float* Wq      = (const float*)d_in[4];
    const float* Wk      = (const float*)d_in[5];
    const float* Wv      = (const float*)d_in[6];
    const float* Wo      = (const float*)d_in[7];
    const float* W_lca   = (const float*)d_in[8];
    const float* W_gate  = (const float*)d_in[9];
    const float* W_up    = (const float*)d_in[10];
    const float* W_down  = (const float*)d_in[11];
    float* out = (float*)d_out;

    float *hn, *q, *k, *v, *attn, *ao, *h, *t1, *b, *u, *a, *gate, *up, *diag;
    float *wqkvT, *woT, *wlT, *wl, *wguT, *wdT;
    cudaGetSymbolAddress((void**)&hn,   g_hn);
    cudaGetSymbolAddress((void**)&q,    g_q);
    cudaGetSymbolAddress((void**)&k,    g_k);
    cudaGetSymbolAddress((void**)&v,    g_v);
    cudaGetSymbolAddress((void**)&attn, g_attn);
    cudaGetSymbolAddress((void**)&ao,   g_ao);
    cudaGetSymbolAddress((void**)&h,    g_h);
    cudaGetSymbolAddress((void**)&t1,   g_t1);
    cudaGetSymbolAddress((void**)&b,    g_b);
    cudaGetSymbolAddress((void**)&u,    g_u);
    cudaGetSymbolAddress((void**)&a,    g_a);
    cudaGetSymbolAddress((void**)&gate, g_gate);
    cudaGetSymbolAddress((void**)&up,   g_up);
    cudaGetSymbolAddress((void**)&diag, g_diag);
    cudaGetSymbolAddress((void**)&wqkvT, g_wqkvT);
    cudaGetSymbolAddress((void**)&woT,   g_woT);
    cudaGetSymbolAddress((void**)&wlT,   g_wlT);
    cudaGetSymbolAddress((void**)&wl,    g_wl);
    cudaGetSymbolAddress((void**)&wguT,  g_wguT);
    cudaGetSymbolAddress((void**)&wdT,   g_wdT);

    cudaFuncSetAttribute(attn_kernel,
                         cudaFuncAttributeMaxDynamicSharedMemorySize, ATTN_SMEM_BYTES);
    cudaFuncSetAttribute(gemm_tf32<0>,
                         cudaFuncAttributeMaxDynamicSharedMemorySize, GEMM_SMEM_BYTES);
    cudaFuncSetAttribute(gemm_tf32<1>,
                         cudaFuncAttributeMaxDynamicSharedMemorySize, GEMM_SMEM_BYTES);
    cudaFuncSetAttribute(gemm_tf32<2>,
                         cudaFuncAttributeMaxDynamicSharedMemorySize, GEMM_SMEM_BYTES);
    cudaFuncSetAttribute(gemm_tf32<3>,
                         cudaFuncAttributeMaxDynamicSharedMemorySize, GEMM_SMEM_BYTES);
    cudaFuncSetAttribute(gemm_tf32<4>,
                         cudaFuncAttributeMaxDynamicSharedMemorySize, GEMM_SMEM_BYTES);
    cudaFuncSetAttribute(gemm_tf32<5>,
                         cudaFuncAttributeMaxDynamicSharedMemorySize, GEMM_SMEM_BYTES);
    cudaFuncSetAttribute(gemm_tf32<6>,
                         cudaFuncAttributeMaxDynamicSharedMemorySize, GEMM_SMEM_BYTES);

    const int NF = NROWS * DFF;
    dim3 tp(32, 8);

    // ---- weight prep: transpose + tf32 round (K-major [N][K]) ----
    transpose_round_kernel<<<dim3(DIM/32,  DIM/32), tp>>>(Wq, wqkvT,                      DIM, DIM);
    transpose_round_kernel<<<dim3(DIM/32,  DIM/32), tp>>>(Wk, wqkvT + (size_t)DIM*DIM,    DIM, DIM);
    transpose_round_kernel<<<dim3(DIM/32,  DIM/32), tp>>>(Wv, wqkvT + (size_t)2*DIM*DIM,  DIM, DIM);
    transpose_round_kernel<<<dim3(DIM/32,  DIM/32), tp>>>(Wo, woT, DIM, DIM);
    transpose_round_kernel<<<dim3(DLCA/32, DIM/32), tp>>>(W_lca, wlT, DIM, DLCA);
    round_tf32_kernel<<<(DIM*DLCA/4 + 255)/256, 256>>>(W_lca, wl, DIM*DLCA/4);
    transpose_round_kernel<<<dim3(DFF/32,  DIM/32), tp>>>(W_gate, wguT,                   DIM, DFF);
    transpose_round_kernel<<<dim3(DFF/32,  DIM/32), tp>>>(W_up,   wguT + (size_t)DFF*DIM, DIM, DFF);
    transpose_round_kernel<<<dim3(DIM/32,  DFF/32), tp>>>(W_down, wdT, DFF, DIM);
    diagG_kernel<<<DLCA / 256, 256>>>(W_lca, diag);

    dim3 gQKV(3*DIM / 128, NROWS / 128);  // (48, 32)
    dim3 gD  (DIM / 128,   NROWS / 128);  // (16, 32)
    dim3 gL  (DLCA / 128,  NROWS / 128);  // (32, 32)
    dim3 gGU (2*DFF / 128, NROWS / 128);  // (128, 32)

    // ---- attention block ----
    rmsnorm_kernel<<<NROWS, 256>>>(x, nullptr, nullptr, w_in, hn);
    gemm_tf32<5><<<gQKV, 128, GEMM_SMEM_BYTES>>>(hn, wqkvT, q, k, v, nullptr, nullptr,
                                                 3*DIM, DIM);
    rope_kernel<<<(NROWS * NH * 64 + 255) / 256, 256>>>(q, k);
    attn_kernel<<<dim3(SQ / 64, NH, BATCH), 256, ATTN_SMEM_BYTES>>>(q, k, v, attn);
    gemm_tf32<0><<<gD, 128, GEMM_SMEM_BYTES>>>(attn, woT, ao, nullptr, nullptr, nullptr,
                                               nullptr, DIM, DIM);

    // ---- LCA block ----  (h = x + ao fused into rmsnorm; init in epilogue)
    rmsnorm_kernel<<<NROWS, 256>>>(x, ao, h, w_lcaN, hn);
    gemm_tf32<2><<<gL, 128, GEMM_SMEM_BYTES>>>(hn, wlT, b, u, a, nullptr, nullptr,
                                               DLCA, DIM);
    for (int it = 0; it < 9; ++it) {
        gemm_tf32<1><<<gD, 128, GEMM_SMEM_BYTES>>>(a, wl, t1, nullptr, nullptr, nullptr,
                                                   nullptr, DIM, DLCA);
        gemm_tf32<3><<<gL, 128, GEMM_SMEM_BYTES>>>(t1, wlT, nullptr, b, u, a, diag,
                                                   DLCA, DIM);
    }
    gemm_tf32<0><<<gD, 128, GEMM_SMEM_BYTES>>>(a, wl, h, nullptr, nullptr, nullptr,
                                               nullptr, DIM, DLCA);

    // ---- MLP block ----
    rmsnorm_kernel<<<NROWS, 256>>>(h, nullptr, nullptr, w_post, hn);
    gemm_tf32<6><<<gGU, 128, GEMM_SMEM_BYTES>>>(hn, wguT, gate, up, nullptr, nullptr,
                                                nullptr, 2*DFF, DIM);
    silu_mul_kernel<<<(NF + 255) / 256, 256>>>(gate, up, NF);
    gemm_tf32<4><<<gD, 128, GEMM_SMEM_BYTES>>>(gate, wdT, out, h, nullptr, nullptr,
                                               nullptr, DIM, DFF);
}

// round 9
// speedup vs baseline: 2.3360x; 1.5180x over previous
#include <cuda_runtime.h>
#include <cuda_fp16.h>
#include <math.h>
#include <stdint.h>

#define SQ    2048
#define DIM   2048
#define NH    16
#define HD    128
#define BATCH 2
#define NROWS 4096      // B*S
#define DLCA  4096
#define DFF   8192

// ---------------- scratch (static device globals; no allocs allowed) -------
// f32 buffers
__device__ float g_q   [(size_t)NROWS*DIM];
__device__ float g_k   [(size_t)NROWS*DIM];
__device__ float g_v   [(size_t)NROWS*DIM];
__device__ float g_ao  [(size_t)NROWS*DIM];
__device__ float g_h   [(size_t)NROWS*DIM];
__device__ float g_b   [(size_t)NROWS*DLCA];
__device__ float g_u   [(size_t)NROWS*DLCA];
__device__ float g_gate[(size_t)NROWS*DFF];
__device__ float g_up  [(size_t)NROWS*DFF];
__device__ float g_diag[DLCA];
// half activation buffers (GEMM A operands)
__device__ __half g_hn [(size_t)NROWS*DIM];
__device__ __half g_at [(size_t)NROWS*DIM];
__device__ __half g_a  [(size_t)NROWS*DLCA];
__device__ __half g_t1 [(size_t)NROWS*DIM];
__device__ __half g_gg [(size_t)NROWS*DFF];
// half weights, K-major [N][K]
__device__ __half g_wqkvT[(size_t)(3*DIM)*DIM];
__device__ __half g_woT  [(size_t)DIM*DIM];
__device__ __half g_wlT  [(size_t)DLCA*DIM];
__device__ __half g_wl   [(size_t)DIM*DLCA];
__device__ __half g_wguT [(size_t)(2*DFF)*DIM];
__device__ __half g_wdT  [(size_t)DIM*DFF];

// ---------------- helpers ----------------------------------------------------
__device__ __forceinline__ __half2 f2h2(float a, float b) {
    return __floats2half2_rn(a, b);
}

#define CP_ASYNC16(dst, src) \
    asm volatile("cp.async.cg.shared.global [%0], [%1], 16;\n" :: "r"(dst), "l"(src))
#define CP_COMMIT() asm volatile("cp.async.commit_group;\n")
#define CP_WAIT1()  asm volatile("cp.async.wait_group 1;\n" ::: "memory")

#define MMA_F16(c, a, b) \
    asm volatile("mma.sync.aligned.m16n8k16.row.col.f32.f16.f16.f32 " \
                 "{%0,%1,%2,%3}, {%4,%5,%6,%7}, {%8,%9}, {%0,%1,%2,%3};" \
                 : "+f"((c)[0]), "+f"((c)[1]), "+f"((c)[2]), "+f"((c)[3]) \
                 : "r"((a)[0]), "r"((a)[1]), "r"((a)[2]), "r"((a)[3]), \
                   "r"((b)[0]), "r"((b)[1]))

// ================= FP16 GEMM (fused epilogues) ==============================
// C[4096,N] = A[4096,K] @ B[N,K]^T  (A,B half, K-major). CTA 128x128, 4 warps
// (2x2), warp tile 64x64, BK=32, 3-stage cp.async, m16n8k16 fp32-accum.
// MODE: 0=f32 store  1=half store (hO)  2=LCA init (C=b,p0=u,hO=a)
//       3=LCA update (p0=b,p1=u,hO=a r/w,dg)  4=residual add (C=acc+p0)
//       5=QKV split (C=q,p0=k,p1=v)           6=gate/up split (C=gate,p0=up)
#define HSTRIDE 40                      // halves per smem row (32 + 8 pad)
#define HFL (128 * HSTRIDE)             // 5120 halves per operand tile
#define HSTG (2 * HFL)                  // 10240 halves per stage
#define GEMM_SMEM_BYTES (3 * HSTG * 2)  // 61440

template<int MODE>
__global__ __launch_bounds__(128, 2) void gemm_f16(
    const __half* __restrict__ A, const __half* __restrict__ B,
    float* __restrict__ C, float* __restrict__ p0, float* __restrict__ p1,
    __half* __restrict__ hO, const float* __restrict__ dg,
    int N, int K)
{
    extern __shared__ __half smh[];
    const int tid  = threadIdx.x;
    const int warp = tid >> 5, lane = tid & 31;
    const int wm = warp & 1, wn = warp >> 1;
    const int g = lane >> 2, q = lane & 3;
    const int bx = blockIdx.x, by = blockIdx.y;

    const size_t ar0 = (size_t)by * 128;
    const size_t br0 = (size_t)bx * 128;
    unsigned smB = (unsigned)__cvta_generic_to_shared(smh);

    float c[4][8][4];
#pragma unroll
    for (int i = 0; i < 4; ++i)
#pragma unroll
        for (int j = 0; j < 8; ++j)
#pragma unroll
            for (int r = 0; r < 4; ++r) c[i][j][r] = 0.f;

    const int T = K >> 5;

    auto load_stage = [&](int t, int s) {
        unsigned base = smB + (unsigned)(s * HSTG) * 2;
        const __half* Ap = A + ar0 * K + (size_t)t * 32;
        const __half* Bp = B + br0 * K + (size_t)t * 32;
#pragma unroll
        for (int i = 0; i < 4; ++i) {
            int u = tid + i * 128;                 // 0..511
            int row = u >> 2, cc = (u & 3) << 3;   // 8 halves = 16B
            CP_ASYNC16(base + (unsigned)(row * HSTRIDE + cc) * 2,
                       Ap + (size_t)row * K + cc);
            CP_ASYNC16(base + (unsigned)(HFL + row * HSTRIDE + cc) * 2,
                       Bp + (size_t)row * K + cc);
        }
    };

    load_stage(0, 0); CP_COMMIT();
    if (T > 1) load_stage(1, 1);
    CP_COMMIT();

    for (int t = 0; t < T; ++t) {
        CP_WAIT1();
        __syncthreads();
        if (t + 2 < T) load_stage(t + 2, (t + 2) % 3);
        CP_COMMIT();

        const __half* As = smh + (t % 3) * HSTG;
        const __half* Bs = As + HFL;

#pragma unroll
        for (int k16 = 0; k16 < 2; ++k16) {
            const int ks = k16 * 16;
            uint32_t a[4][4], b[8][2];
#pragma unroll
            for (int mi = 0; mi < 4; ++mi) {
                int r0 = wm * 64 + mi * 16 + g;
                a[mi][0] = *(const uint32_t*)(As + r0 * HSTRIDE + ks + 2 * q);
                a[mi][1] = *(const uint32_t*)(As + (r0 + 8) * HSTRIDE + ks + 2 * q);
                a[mi][2] = *(const uint32_t*)(As + r0 * HSTRIDE + ks + 2 * q + 8);
                a[mi][3] = *(const uint32_t*)(As + (r0 + 8) * HSTRIDE + ks + 2 * q + 8);
            }
#pragma unroll
            for (int ni = 0; ni < 8; ++ni) {
                int cn = wn * 64 + ni * 8 + g;
                b[ni][0] = *(const uint32_t*)(Bs + cn * HSTRIDE + ks + 2 * q);
                b[ni][1] = *(const uint32_t*)(Bs + cn * HSTRIDE + ks + 2 * q + 8);
            }
#pragma unroll
            for (int mi = 0; mi < 4; ++mi)
#pragma unroll
                for (int ni = 0; ni < 8; ++ni)
                    MMA_F16(c[mi][ni], a[mi], b[ni]);
        }
    }

    // ---------------- templated epilogue -----------------------------------
    float* Cout = C;
    int Nout = N, colsub = 0;
    if constexpr (MODE == 5) {
        int which = (int)(br0 >> 11);
        Cout = (which == 0) ? C : (which == 1 ? p0 : p1);
        Nout = 2048; colsub = which * 2048;
    }
    if constexpr (MODE == 6) {
        int which = (int)(br0 >> 13);
        Cout = which ? p0 : C;
        Nout = 8192; colsub = which * 8192;
    }

#pragma unroll
    for (int mi = 0; mi < 4; ++mi) {
        int row0 = (int)ar0 + wm * 64 + mi * 16 + g;
#pragma unroll
        for (int ni = 0; ni < 8; ++ni) {
            int col = (int)br0 + wn * 64 + ni * 8 + q * 2;
#pragma unroll
            for (int hh = 0; hh < 2; ++hh) {
                int r = row0 + hh * 8;
                float v0 = c[mi][ni][hh * 2 + 0];
                float v1 = c[mi][ni][hh * 2 + 1];
                if constexpr (MODE == 0) {
                    *(float2*)(C + (size_t)r * N + col) = make_float2(v0, v1);
                } else if constexpr (MODE == 1) {
                    *(__half2*)(hO + (size_t)r * N + col) = f2h2(v0, v1);
                } else if constexpr (MODE == 2) {
                    size_t i0 = (size_t)r * N + col;
                    *(float2*)(C + i0) = make_float2(v0, v1);        // b
                    float u0 = 0.1f * v0, u1 = 0.1f * v1;
                    *(float2*)(p0 + i0) = make_float2(u0, u1);       // u
                    *(__half2*)(hO + i0) = f2h2(fmaxf(u0 - 0.1f, 0.f),
                                                fmaxf(u1 - 0.1f, 0.f));
                } else if constexpr (MODE == 3) {
                    size_t i0 = (size_t)r * N + col;
                    float2 dgv = *(const float2*)(dg + col);
                    __half2 ah = *(const __half2*)(hO + i0);
                    float2 av = __half22float2(ah);
                    float2 bb = *(const float2*)(p0 + i0);
                    float2 uv = *(const float2*)(p1 + i0);
                    float inh0 = v0 - av.x * dgv.x;
                    float inh1 = v1 - av.y * dgv.y;
                    uv.x += 0.1f * (bb.x - inh0 - uv.x);
                    uv.y += 0.1f * (bb.y - inh1 - uv.y);
                    *(float2*)(p1 + i0) = uv;
                    *(__half2*)(hO + i0) = f2h2(fmaxf(uv.x - 0.1f, 0.f),
                                                fmaxf(uv.y - 0.1f, 0.f));
                } else if constexpr (MODE == 4) {
                    size_t i0 = (size_t)r * N + col;
                    float2 rv = *(const float2*)(p0 + i0);
                    *(float2*)(C + i0) = make_float2(v0 + rv.x, v1 + rv.y);
                } else {  // 5 / 6
                    *(float2*)(Cout + (size_t)r * Nout + (col - colsub)) =
                        make_float2(v0, v1);
                }
            }
        }
    }
}

// ---------------- weight prep ----------------------------------------------
// W[K,N] f32 -> T[N][K] half
__global__ void transpose_half_kernel(const float* __restrict__ W,
                                      __half* __restrict__ To, int K, int N)
{
    __shared__ float tsm[32][33];
    int n0 = blockIdx.x * 32, k0 = blockIdx.y * 32;
    int tx = threadIdx.x, ty = threadIdx.y;   // 32 x 8
#pragma unroll
    for (int i = 0; i < 4; ++i)
        tsm[ty + i * 8][tx] = W[(size_t)(k0 + ty + i * 8) * N + n0 + tx];
    __syncthreads();
#pragma unroll
    for (int i = 0; i < 4; ++i) {
        int n = n0 + ty + i * 8;
        To[(size_t)n * K + k0 + tx] = __float2half_rn(tsm[tx][ty + i * 8]);
    }
}

__global__ void round_half_kernel(const float* __restrict__ s, __half* __restrict__ d, int n)
{
    int i = blockIdx.x * blockDim.x + threadIdx.x;
    if (i < n) d[i] = __float2half_rn(s[i]);
}

// diag of Wh^T Wh using the half-rounded weights (matches GEMM exactly)
__global__ void diagG_kernel(const __half* __restrict__ Wh, float* __restrict__ diag)
{
    int j = blockIdx.x * blockDim.x + threadIdx.x;
    if (j < DLCA) {
        float s = 0.f;
        for (int i = 0; i < DIM; ++i) {
            float w = __half2float(Wh[(size_t)i * DLCA + j]);
            s = fmaf(w, w, s);
        }
        diag[j] = s;
    }
}

// ---------------- RMSNorm (emits half) --------------------------------------
__global__ __launch_bounds__(256) void rmsnorm_kernel(
    const float* __restrict__ x, const float* __restrict__ res,
    float* __restrict__ hsum, const float* __restrict__ w, __half* __restrict__ out)
{
    __shared__ float red[8];
    int row = blockIdx.x, tid = threadIdx.x;
    const float* xr = x + (size_t)row * DIM;
    float4 v[2];
    float ss = 0.f;
#pragma unroll
    for (int p = 0; p < 2; ++p) {
        int cix = p * 1024 + tid * 4;
        v[p] = *(const float4*)(xr + cix);
        if (res) {
            float4 rv = *(const float4*)(res + (size_t)row * DIM + cix);
            v[p].x += rv.x; v[p].y += rv.y; v[p].z += rv.z; v[p].w += rv.w;
            *(float4*)(hsum + (size_t)row * DIM + cix) = v[p];
        }
        ss += v[p].x * v[p].x + v[p].y * v[p].y + v[p].z * v[p].z + v[p].w * v[p].w;
    }
#pragma unroll
    for (int off = 16; off; off >>= 1) ss += __shfl_xor_sync(~0u, ss, off);
    if ((tid & 31) == 0) red[tid >> 5] = ss;
    __syncthreads();
    if (tid == 0) {
        float t = 0.f;
#pragma unroll
        for (int i = 0; i < 8; ++i) t += red[i];
        red[0] = rsqrtf(t / (float)DIM + 1e-6f);
    }
    __syncthreads();
    float inv = red[0];
#pragma unroll
    for (int p = 0; p < 2; ++p) {
        int cix = p * 1024 + tid * 4;
        float4 wv = *(const float4*)(w + cix);
        __half2 h01 = f2h2(v[p].x * inv * wv.x, v[p].y * inv * wv.y);
        __half2 h23 = f2h2(v[p].z * inv * wv.z, v[p].w * inv * wv.w);
        *(uint2*)(out + (size_t)row * DIM + cix) =
            make_uint2(*(uint32_t*)&h01, *(uint32_t*)&h23);
    }
}

// ---------------- RoPE (in-place on q and k, f32) ---------------------------
__global__ void rope_kernel(float* __restrict__ q, float* __restrict__ k)
{
    int idx = blockIdx.x * blockDim.x + threadIdx.x;
    if (idx >= NROWS * NH * 64) return;
    int i   = idx & 63;
    int h   = (idx >> 6) & (NH - 1);
    int row = idx >> 10;
    int pos = row & (SQ - 1);
    float inv = (float)exp(-((double)(2 * i) / (double)HD) * 9.210340371976184);
    float ang = (float)pos * inv;
    float sn, cs;
    sincosf(ang, &sn, &cs);
    size_t base = (size_t)row * DIM + (size_t)h * HD;
    float a = q[base + i], b = q[base + i + 64];
    q[base + i]      = a * cs - b * sn;
    q[base + i + 64] = b * cs + a * sn;
    a = k[base + i]; b = k[base + i + 64];
    k[base + i]      = a * cs - b * sn;
    k[base + i + 64] = b * cs + a * sn;
}

// ---------------- Flash attention (causal, f32 math, half out) --------------
#define ATTN_SMEM_FLOATS (64*128 + 64*132 + 64*128 + 64*64)
#define ATTN_SMEM_BYTES  (ATTN_SMEM_FLOATS * 4)

__global__ __launch_bounds__(256) void attn_kernel(
    const float* __restrict__ Q, const float* __restrict__ K,
    const float* __restrict__ V, __half* __restrict__ O)
{
    extern __shared__ float smf[];
    float* Qs = smf;
    float* Ks = smf + 8192;
    float* Vs = smf + 8192 + 8448;
    float* Ps = smf + 8192 + 8448 + 8192;

    int qt = blockIdx.x, h = blockIdx.y, b = blockIdx.z;
    int tid = threadIdx.x;
    int ty = tid >> 4, tx = tid & 15;
    int qr0 = ty * 4;
    int dc0 = tx * 8;

    const float* Qb = Q + (size_t)b * SQ * DIM + (size_t)h * HD;
    const float* Kb = K + (size_t)b * SQ * DIM + (size_t)h * HD;
    const float* Vb = V + (size_t)b * SQ * DIM + (size_t)h * HD;

    for (int i = tid; i < 64 * 32; i += 256) {
        int r = i >> 5, cix = (i & 31) << 2;
        *(float4*)&Qs[r * 128 + cix] =
            *(const float4*)(Qb + (size_t)(qt * 64 + r) * DIM + cix);
    }

    float m[4], l[4], o[4][8];
#pragma unroll
    for (int i = 0; i < 4; ++i) {
        m[i] = -3.0e38f; l[i] = 0.f;
#pragma unroll
        for (int d = 0; d < 8; ++d) o[i][d] = 0.f;
    }
    __syncthreads();

    const float SCALE = 0.08838834764831845f;

    for (int kt = 0; kt <= qt; ++kt) {
        for (int i = tid; i < 64 * 32; i += 256) {
            int r = i >> 5, cix = (i & 31) << 2;
            *(float4*)&Ks[r * 132 + cix] =
                *(const float4*)(Kb + (size_t)(kt * 64 + r) * DIM + cix);
            *(float4*)&Vs[r * 128 + cix] =
                *(const float4*)(Vb + (size_t)(kt * 64 + r) * DIM + cix);
        }
        __syncthreads();

        float s[4][4];
#pragma unroll
        for (int i = 0; i < 4; ++i)
#pragma unroll
            for (int j = 0; j < 4; ++j) s[i][j] = 0.f;

        for (int d0 = 0; d0 < HD; d0 += 4) {
            float4 kf[4];
#pragma unroll
            for (int j = 0; j < 4; ++j)
                kf[j] = *(const float4*)&Ks[(tx + 16 * j) * 132 + d0];
#pragma unroll
            for (int i = 0; i < 4; ++i) {
                float4 qf = *(const float4*)&Qs[(qr0 + i) * 128 + d0];
#pragma unroll
                for (int j = 0; j < 4; ++j) {
                    s[i][j] = fmaf(qf.x, kf[j].x, s[i][j]);
                    s[i][j] = fmaf(qf.y, kf[j].y, s[i][j]);
                    s[i][j] = fmaf(qf.z, kf[j].z, s[i][j]);
                    s[i][j] = fmaf(qf.w, kf[j].w, s[i][j]);
                }
            }
        }

#pragma unroll
        for (int i = 0; i < 4; ++i)
#pragma unroll
            for (int j = 0; j < 4; ++j) s[i][j] *= SCALE;

        if (kt == qt) {
#pragma unroll
            for (int i = 0; i < 4; ++i) {
                int qidx = qt * 64 + qr0 + i;
#pragma unroll
                for (int j = 0; j < 4; ++j) {
                    int kidx = kt * 64 + tx + 16 * j;
                    if (kidx > qidx) s[i][j] = -1e30f;
                }
            }
        }

#pragma unroll
        for (int i = 0; i < 4; ++i) {
            float mr = fmaxf(fmaxf(s[i][0], s[i][1]), fmaxf(s[i][2], s[i][3]));
#pragma unroll
            for (int off = 1; off < 16; off <<= 1)
                mr = fmaxf(mr, __shfl_xor_sync(~0u, mr, off));
            float mn = fmaxf(m[i], mr);
            float corr = __expf(m[i] - mn);
            m[i] = mn;
            float p0 = __expf(s[i][0] - mn);
            float p1 = __expf(s[i][1] - mn);
            float p2 = __expf(s[i][2] - mn);
            float p3 = __expf(s[i][3] - mn);
            float ls = p0 + p1 + p2 + p3;
#pragma unroll
            for (int off = 1; off < 16; off <<= 1)
                ls += __shfl_xor_sync(~0u, ls, off);
            l[i] = l[i] * corr + ls;
#pragma unroll
            for (int d = 0; d < 8; ++d) o[i][d] *= corr;
            Ps[(qr0 + i) * 64 + tx]      = p0;
            Ps[(qr0 + i) * 64 + tx + 16] = p1;
            Ps[(qr0 + i) * 64 + tx + 32] = p2;
            Ps[(qr0 + i) * 64 + tx + 48] = p3;
        }
        __syncthreads();

        for (int kk = 0; kk < 64; ++kk) {
            float4 v0 = *(const float4*)&Vs[kk * 128 + dc0];
            float4 v1 = *(const float4*)&Vs[kk * 128 + dc0 + 4];
#pragma unroll
            for (int i = 0; i < 4; ++i) {
                float p = Ps[(qr0 + i) * 64 + kk];
                o[i][0] = fmaf(p, v0.x, o[i][0]);
                o[i][1] = fmaf(p, v0.y, o[i][1]);
                o[i][2] = fmaf(p, v0.z, o[i][2]);
                o[i][3] = fmaf(p, v0.w, o[i][3]);
                o[i][4] = fmaf(p, v1.x, o[i][4]);
                o[i][5] = fmaf(p, v1.y, o[i][5]);
                o[i][6] = fmaf(p, v1.z, o[i][6]);
                o[i][7] = fmaf(p, v1.w, o[i][7]);
            }
        }
        __syncthreads();
    }

    // half output (feeds Wo GEMM)
#pragma unroll
    for (int i = 0; i < 4; ++i) {
        float inv = 1.f / l[i];
        int row = qt * 64 + qr0 + i;
        __half* op = O + (size_t)(b * SQ + row) * DIM + (size_t)h * HD + dc0;
        __half2 h0 = f2h2(o[i][0] * inv, o[i][1] * inv);
        __half2 h1 = f2h2(o[i][2] * inv, o[i][3] * inv);
        __half2 h2 = f2h2(o[i][4] * inv, o[i][5] * inv);
        __half2 h3 = f2h2(o[i][6] * inv, o[i][7] * inv);
        *(uint4*)op = make_uint4(*(uint32_t*)&h0, *(uint32_t*)&h1,
                                 *(uint32_t*)&h2, *(uint32_t*)&h3);
    }
}

// ---------------- elementwise ----------------------------------------------
__global__ void silu_mul_kernel(const float* __restrict__ gte, const float* __restrict__ up,
                                __half* __restrict__ gg, int n)
{
    int i = blockIdx.x * blockDim.x + threadIdx.x;
    if (i < n) {
        float x = gte[i];
        float sig = 1.f / (1.f + expf(-x));
        gg[i] = __float2half_rn(x * sig * up[i]);
    }
}

// ---------------- launch ----------------------------------------------------
extern "C" void kernel_launch(void* const* d_in, const int* in_sizes, int n_in,
                              void* d_out, int out_size)
{
    const float* x       = (const float*)d_in[0];
    const float* w_in    = (const float*)d_in[1];
    const float* w_lcaN  = (const float*)d_in[2];
    const float* w_post  = (const float*)d_in[3];
    const float* Wq      = (const float*)d_in[4];
    const float* Wk      = (const float*)d_in[5];
    const float* Wv      = (const float*)d_in[6];
    const float* Wo      = (const float*)d_in[7];
    const float* W_lca   = (const float*)d_in[8];
    const float* W_gate  = (const float*)d_in[9];
    const float* W_up    = (const float*)d_in[10];
    const float* W_down  = (const float*)d_in[11];
    float* out = (float*)d_out;

    float *q, *k, *v, *ao, *h, *b, *u, *gate, *up, *diag;
    __half *hn, *at, *a, *t1, *gg;
    __half *wqkvT, *woT, *wlT, *wl, *wguT, *wdT;
    cudaGetSymbolAddress((void**)&q,    g_q);
    cudaGetSymbolAddress((void**)&k,    g_k);
    cudaGetSymbolAddress((void**)&v,    g_v);
    cudaGetSymbolAddress((void**)&ao,   g_ao);
    cudaGetSymbolAddress((void**)&h,    g_h);
    cudaGetSymbolAddress((void**)&b,    g_b);
    cudaGetSymbolAddress((void**)&u,    g_u);
    cudaGetSymbolAddress((void**)&gate, g_gate);
    cudaGetSymbolAddress((void**)&up,   g_up);
    cudaGetSymbolAddress((void**)&diag, g_diag);
    cudaGetSymbolAddress((void**)&hn,   g_hn);
    cudaGetSymbolAddress((void**)&at,   g_at);
    cudaGetSymbolAddress((void**)&a,    g_a);
    cudaGetSymbolAddress((void**)&t1,   g_t1);
    cudaGetSymbolAddress((void**)&gg,   g_gg);
    cudaGetSymbolAddress((void**)&wqkvT, g_wqkvT);
    cudaGetSymbolAddress((void**)&woT,   g_woT);
    cudaGetSymbolAddress((void**)&wlT,   g_wlT);
    cudaGetSymbolAddress((void**)&wl,    g_wl);
    cudaGetSymbolAddress((void**)&wguT,  g_wguT);
    cudaGetSymbolAddress((void**)&wdT,   g_wdT);

    cudaFuncSetAttribute(attn_kernel,
                         cudaFuncAttributeMaxDynamicSharedMemorySize, ATTN_SMEM_BYTES);
    cudaFuncSetAttribute(gemm_f16<0>,
                         cudaFuncAttributeMaxDynamicSharedMemorySize, GEMM_SMEM_BYTES);
    cudaFuncSetAttribute(gemm_f16<1>,
                         cudaFuncAttributeMaxDynamicSharedMemorySize, GEMM_SMEM_BYTES);
    cudaFuncSetAttribute(gemm_f16<2>,
                         cudaFuncAttributeMaxDynamicSharedMemorySize, GEMM_SMEM_BYTES);
    cudaFuncSetAttribute(gemm_f16<3>,
                         cudaFuncAttributeMaxDynamicSharedMemorySize, GEMM_SMEM_BYTES);
    cudaFuncSetAttribute(gemm_f16<4>,
                         cudaFuncAttributeMaxDynamicSharedMemorySize, GEMM_SMEM_BYTES);
    cudaFuncSetAttribute(gemm_f16<5>,
                         cudaFuncAttributeMaxDynamicSharedMemorySize, GEMM_SMEM_BYTES);
    cudaFuncSetAttribute(gemm_f16<6>,
                         cudaFuncAttributeMaxDynamicSharedMemorySize, GEMM_SMEM_BYTES);

    const int NF = NROWS * DFF;
    dim3 tp(32, 8);

    // ---- weight prep: transpose + half (K-major [N][K]) ----
    transpose_half_kernel<<<dim3(DIM/32,  DIM/32), tp>>>(Wq, wqkvT,                      DIM, DIM);
    transpose_half_kernel<<<dim3(DIM/32,  DIM/32), tp>>>(Wk, wqkvT + (size_t)DIM*DIM,    DIM, DIM);
    transpose_half_kernel<<<dim3(DIM/32,  DIM/32), tp>>>(Wv, wqkvT + (size_t)2*DIM*DIM,  DIM, DIM);
    transpose_half_kernel<<<dim3(DIM/32,  DIM/32), tp>>>(Wo, woT, DIM, DIM);
    transpose_half_kernel<<<dim3(DLCA/32, DIM/32), tp>>>(W_lca, wlT, DIM, DLCA);
    round_half_kernel<<<(DIM*DLCA + 255)/256, 256>>>(W_lca, wl, DIM*DLCA);
    transpose_half_kernel<<<dim3(DFF/32,  DIM/32), tp>>>(W_gate, wguT,                   DIM, DFF);
    transpose_half_kernel<<<dim3(DFF/32,  DIM/32), tp>>>(W_up,   wguT + (size_t)DFF*DIM, DIM, DFF);
    transpose_half_kernel<<<dim3(DIM/32,  DFF/32), tp>>>(W_down, wdT, DFF, DIM);
    diagG_kernel<<<DLCA / 256, 256>>>(wl, diag);

    dim3 gQKV(3*DIM / 128, NROWS / 128);
    dim3 gD  (DIM / 128,   NROWS / 128);
    dim3 gL  (DLCA / 128,  NROWS / 128);
    dim3 gGU (2*DFF / 128, NROWS / 128);

    // ---- attention block ----
    rmsnorm_kernel<<<NROWS, 256>>>(x, nullptr, nullptr, w_in, hn);
    gemm_f16<5><<<gQKV, 128, GEMM_SMEM_BYTES>>>(hn, wqkvT, q, k, v, nullptr, nullptr,
                                                3*DIM, DIM);
    rope_kernel<<<(NROWS * NH * 64 + 255) / 256, 256>>>(q, k);
    attn_kernel<<<dim3(SQ / 64, NH, BATCH), 256, ATTN_SMEM_BYTES>>>(q, k, v, at);
    gemm_f16<0><<<gD, 128, GEMM_SMEM_BYTES>>>(at, woT, ao, nullptr, nullptr, nullptr,
                                              nullptr, DIM, DIM);

    // ---- LCA block ----
    rmsnorm_kernel<<<NROWS, 256>>>(x, ao, h, w_lcaN, hn);
    gemm_f16<2><<<gL, 128, GEMM_SMEM_BYTES>>>(hn, wlT, b, u, nullptr, a, nullptr,
                                              DLCA, DIM);
    for (int it = 0; it < 9; ++it) {
        gemm_f16<1><<<gD, 128, GEMM_SMEM_BYTES>>>(a, wl, nullptr, nullptr, nullptr, t1,
                                                  nullptr, DIM, DLCA);
        gemm_f16<3><<<gL, 128, GEMM_SMEM_BYTES>>>(t1, wlT, nullptr, b, u, a, diag,
                                                  DLCA, DIM);
    }
    gemm_f16<0><<<gD, 128, GEMM_SMEM_BYTES>>>(a, wl, h, nullptr, nullptr, nullptr,
                                              nullptr, DIM, DLCA);

    // ---- MLP block ----
    rmsnorm_kernel<<<NROWS, 256>>>(h, nullptr, nullptr, w_post, hn);
    gemm_f16<6><<<gGU, 128, GEMM_SMEM_BYTES>>>(hn, wguT, gate, up, nullptr, nullptr,
                                               nullptr, 2*DFF, DIM);
    silu_mul_kernel<<<(NF + 255) / 256, 256>>>(gate, up, gg, NF);
    gemm_f16<4><<<gD, 128, GEMM_SMEM_BYTES>>>(gg, wdT, out, h, nullptr, nullptr,
                                              nullptr, DIM, DFF);
}

// round 12
// speedup vs baseline: 2.7076x; 1.1590x over previous
#include <cuda_runtime.h>
#include <cuda_fp16.h>
#include <math.h>
#include <stdint.h>

#define SQ    2048
#define DIM   2048
#define NH    16
#define HD    128
#define BATCH 2
#define NROWS 4096      // B*S
#define DLCA  4096
#define DFF   8192

// ---------------- scratch (static device globals; no allocs allowed) -------
__device__ float g_q   [(size_t)NROWS*DIM];
__device__ float g_k   [(size_t)NROWS*DIM];
__device__ float g_v   [(size_t)NROWS*DIM];
__device__ float g_ao  [(size_t)NROWS*DIM];
__device__ float g_h   [(size_t)NROWS*DIM];
__device__ float g_b   [(size_t)NROWS*DLCA];
__device__ float g_u   [(size_t)NROWS*DLCA];
__device__ float g_gate[(size_t)NROWS*DFF];
__device__ float g_up  [(size_t)NROWS*DFF];
__device__ float g_diag[DLCA];
// half activation buffers (GEMM A operands)
__device__ __half g_hn [(size_t)NROWS*DIM];
__device__ __half g_at [(size_t)NROWS*DIM];
__device__ __half g_a  [(size_t)NROWS*DLCA];
__device__ __half g_t1 [(size_t)NROWS*DIM];
__device__ __half g_gg [(size_t)NROWS*DFF];
// half weights, K-major [N][K]
__device__ __half g_wqkvT[(size_t)(3*DIM)*DIM];
__device__ __half g_woT  [(size_t)DIM*DIM];
__device__ __half g_wlT  [(size_t)DLCA*DIM];
__device__ __half g_wl   [(size_t)DIM*DLCA];
__device__ __half g_wguT [(size_t)(2*DFF)*DIM];
__device__ __half g_wdT  [(size_t)DIM*DFF];

// ---------------- helpers ----------------------------------------------------
__device__ __forceinline__ __half2 f2h2(float a, float b) {
    return __floats2half2_rn(a, b);
}

#define CP_ASYNC16(dst, src) \
    asm volatile("cp.async.cg.shared.global [%0], [%1], 16;\n" :: "r"(dst), "l"(src))
#define CP_COMMIT() asm volatile("cp.async.commit_group;\n")
#define CP_WAIT1()  asm volatile("cp.async.wait_group 1;\n" ::: "memory")

#define MMA_F16(c, a0, a1, a2, a3, b0, b1) \
    asm volatile("mma.sync.aligned.m16n8k16.row.col.f32.f16.f16.f32 " \
                 "{%0,%1,%2,%3}, {%4,%5,%6,%7}, {%8,%9}, {%0,%1,%2,%3};" \
                 : "+f"((c)[0]), "+f"((c)[1]), "+f"((c)[2]), "+f"((c)[3]) \
                 : "r"(a0), "r"(a1), "r"(a2), "r"(a3), "r"(b0), "r"(b1))

#define LDSM4(r0, r1, r2, r3, adr) \
    asm volatile("ldmatrix.sync.aligned.m8n8.x4.shared.b16 {%0,%1,%2,%3}, [%4];" \
                 : "=r"(r0), "=r"(r1), "=r"(r2), "=r"(r3) : "r"(adr))

// ================= FP16 GEMM (ldmatrix + fused epilogues) ===================
// C[4096,N] = A[4096,K] @ B[N,K]^T  (A,B half, K-major). CTA 128x128, 4 warps
// (2x2), warp tile 64x64, BK=32, 3-stage cp.async, m16n8k16 fp32-accum.
// MODE: 0=f32 store  1=half store (hO)  2=LCA init (C=b,p0=u,hO=a)
//       3=LCA update (p0=b,p1=u,hO=a r/w,dg)  4=residual add (C=acc+p0)
//       5=QKV split (C=q,p0=k,p1=v)           6=gate/up split (C=gate,p0=up)
#define HSTRIDE 40                      // halves per smem row (32 + 8 pad)
#define HFL (128 * HSTRIDE)             // 5120 halves per operand tile
#define HSTG (2 * HFL)                  // 10240 halves per stage
#define GEMM_SMEM_BYTES (3 * HSTG * 2)  // 61440

template<int MODE>
__global__ __launch_bounds__(128, 2) void gemm_f16(
    const __half* __restrict__ A, const __half* __restrict__ B,
    float* __restrict__ C, float* __restrict__ p0, float* __restrict__ p1,
    __half* __restrict__ hO, const float* __restrict__ dg,
    int N, int K)
{
    extern __shared__ __half smh[];
    const int tid  = threadIdx.x;
    const int warp = tid >> 5, lane = tid & 31;
    const int wm = warp & 1, wn = warp >> 1;
    const int g = lane >> 2, q = lane & 3;
    const int bx = blockIdx.x, by = blockIdx.y;

    const size_t ar0 = (size_t)by * 128;
    const size_t br0 = (size_t)bx * 128;
    unsigned smB = (unsigned)__cvta_generic_to_shared(smh);

    // ldmatrix per-lane source offsets
    const int aRow = wm * 64 + (lane & 15);
    const int aK8  = 8 * (lane >> 4);
    const int bRow = wn * 64 + ((lane >> 4) << 3) + (lane & 7);
    const int bK8  = 8 * ((lane >> 3) & 1);

    float c[4][8][4];
#pragma unroll
    for (int i = 0; i < 4; ++i)
#pragma unroll
        for (int j = 0; j < 8; ++j)
#pragma unroll
            for (int r = 0; r < 4; ++r) c[i][j][r] = 0.f;

    const int T = K >> 5;

    auto load_stage = [&](int t, int s) {
        unsigned base = smB + (unsigned)(s * HSTG) * 2;
        const __half* Ap = A + ar0 * K + (size_t)t * 32;
        const __half* Bp = B + br0 * K + (size_t)t * 32;
#pragma unroll
        for (int i = 0; i < 4; ++i) {
            int u = tid + i * 128;                 // 0..511
            int row = u >> 2, cc = (u & 3) << 3;   // 8 halves = 16B
            CP_ASYNC16(base + (unsigned)(row * HSTRIDE + cc) * 2,
                       Ap + (size_t)row * K + cc);
            CP_ASYNC16(base + (unsigned)(HFL + row * HSTRIDE + cc) * 2,
                       Bp + (size_t)row * K + cc);
        }
    };

    load_stage(0, 0); CP_COMMIT();
    if (T > 1) load_stage(1, 1);
    CP_COMMIT();

    for (int t = 0; t < T; ++t) {
        CP_WAIT1();
        __syncthreads();
        if (t + 2 < T) load_stage(t + 2, (t + 2) % 3);
        CP_COMMIT();

        unsigned stB = smB + (unsigned)((t % 3) * HSTG) * 2;

#pragma unroll
        for (int k16 = 0; k16 < 2; ++k16) {
            const int ks = k16 * 16;
            uint32_t a[4][4], b[4][4];
#pragma unroll
            for (int mi = 0; mi < 4; ++mi) {
                unsigned adr = stB +
                    (unsigned)(((aRow + mi * 16) * HSTRIDE) + ks + aK8) * 2;
                LDSM4(a[mi][0], a[mi][1], a[mi][2], a[mi][3], adr);
            }
#pragma unroll
            for (int nj = 0; nj < 4; ++nj) {
                unsigned adr = stB + (unsigned)(HFL * 2) +
                    (unsigned)(((bRow + nj * 16) * HSTRIDE) + ks + bK8) * 2;
                LDSM4(b[nj][0], b[nj][1], b[nj][2], b[nj][3], adr);
            }
#pragma unroll
            for (int mi = 0; mi < 4; ++mi)
#pragma unroll
                for (int nj = 0; nj < 4; ++nj) {
                    MMA_F16(c[mi][2 * nj],
                            a[mi][0], a[mi][1], a[mi][2], a[mi][3],
                            b[nj][0], b[nj][1]);
                    MMA_F16(c[mi][2 * nj + 1],
                            a[mi][0], a[mi][1], a[mi][2], a[mi][3],
                            b[nj][2], b[nj][3]);
                }
        }
    }

    // ---------------- templated epilogue -----------------------------------
    float* Cout = C;
    int Nout = N, colsub = 0;
    if constexpr (MODE == 5) {
        int which = (int)(br0 >> 11);
        Cout = (which == 0) ? C : (which == 1 ? p0 : p1);
        Nout = 2048; colsub = which * 2048;
    }
    if constexpr (MODE == 6) {
        int which = (int)(br0 >> 13);
        Cout = which ? p0 : C;
        Nout = 8192; colsub = which * 8192;
    }

#pragma unroll
    for (int mi = 0; mi < 4; ++mi) {
        int row0 = (int)ar0 + wm * 64 + mi * 16 + g;
#pragma unroll
        for (int ni = 0; ni < 8; ++ni) {
            int col = (int)br0 + wn * 64 + ni * 8 + q * 2;
#pragma unroll
            for (int hh = 0; hh < 2; ++hh) {
                int r = row0 + hh * 8;
                float v0 = c[mi][ni][hh * 2 + 0];
                float v1 = c[mi][ni][hh * 2 + 1];
                if constexpr (MODE == 0) {
                    *(float2*)(C + (size_t)r * N + col) = make_float2(v0, v1);
                } else if constexpr (MODE == 1) {
                    *(__half2*)(hO + (size_t)r * N + col) = f2h2(v0, v1);
                } else if constexpr (MODE == 2) {
                    size_t i0 = (size_t)r * N + col;
                    *(float2*)(C + i0) = make_float2(v0, v1);        // b
                    float u0 = 0.1f * v0, u1 = 0.1f * v1;
                    *(float2*)(p0 + i0) = make_float2(u0, u1);       // u
                    *(__half2*)(hO + i0) = f2h2(fmaxf(u0 - 0.1f, 0.f),
                                                fmaxf(u1 - 0.1f, 0.f));
                } else if constexpr (MODE == 3) {
                    size_t i0 = (size_t)r * N + col;
                    float2 dgv = *(const float2*)(dg + col);
                    __half2 ah = *(const __half2*)(hO + i0);
                    float2 av = __half22float2(ah);
                    float2 bb = *(const float2*)(p0 + i0);
                    float2 uv = *(const float2*)(p1 + i0);
                    float inh0 = v0 - av.x * dgv.x;
                    float inh1 = v1 - av.y * dgv.y;
                    uv.x += 0.1f * (bb.x - inh0 - uv.x);
                    uv.y += 0.1f * (bb.y - inh1 - uv.y);
                    *(float2*)(p1 + i0) = uv;
                    *(__half2*)(hO + i0) = f2h2(fmaxf(uv.x - 0.1f, 0.f),
                                                fmaxf(uv.y - 0.1f, 0.f));
                } else if constexpr (MODE == 4) {
                    size_t i0 = (size_t)r * N + col;
                    float2 rv = *(const float2*)(p0 + i0);
                    *(float2*)(C + i0) = make_float2(v0 + rv.x, v1 + rv.y);
                } else {  // 5 / 6
                    *(float2*)(Cout + (size_t)r * Nout + (col - colsub)) =
                        make_float2(v0, v1);
                }
            }
        }
    }
}

// ---------------- weight prep ----------------------------------------------
__global__ void transpose_half_kernel(const float* __restrict__ W,
                                      __half* __restrict__ To, int K, int N)
{
    __shared__ float tsm[32][33];
    int n0 = blockIdx.x * 32, k0 = blockIdx.y * 32;
    int tx = threadIdx.x, ty = threadIdx.y;   // 32 x 8
#pragma unroll
    for (int i = 0; i < 4; ++i)
        tsm[ty + i * 8][tx] = W[(size_t)(k0 + ty + i * 8) * N + n0 + tx];
    __syncthreads();
#pragma unroll
    for (int i = 0; i < 4; ++i) {
        int n = n0 + ty + i * 8;
        To[(size_t)n * K + k0 + tx] = __float2half_rn(tsm[tx][ty + i * 8]);
    }
}

__global__ void round_half_kernel(const float* __restrict__ s, __half* __restrict__ d, int n)
{
    int i = blockIdx.x * blockDim.x + threadIdx.x;
    if (i < n) d[i] = __float2half_rn(s[i]);
}

__global__ void diagG_kernel(const __half* __restrict__ Wh, float* __restrict__ diag)
{
    int j = blockIdx.x * blockDim.x + threadIdx.x;
    if (j < DLCA) {
        float s = 0.f;
        for (int i = 0; i < DIM; ++i) {
            float w = __half2float(Wh[(size_t)i * DLCA + j]);
            s = fmaf(w, w, s);
        }
        diag[j] = s;
    }
}

// ---------------- RMSNorm (emits half) --------------------------------------
__global__ __launch_bounds__(256) void rmsnorm_kernel(
    const float* __restrict__ x, const float* __restrict__ res,
    float* __restrict__ hsum, const float* __restrict__ w, __half* __restrict__ out)
{
    __shared__ float red[8];
    int row = blockIdx.x, tid = threadIdx.x;
    const float* xr = x + (size_t)row * DIM;
    float4 v[2];
    float ss = 0.f;
#pragma unroll
    for (int p = 0; p < 2; ++p) {
        int cix = p * 1024 + tid * 4;
        v[p] = *(const float4*)(xr + cix);
        if (res) {
            float4 rv = *(const float4*)(res + (size_t)row * DIM + cix);
            v[p].x += rv.x; v[p].y += rv.y; v[p].z += rv.z; v[p].w += rv.w;
            *(float4*)(hsum + (size_t)row * DIM + cix) = v[p];
        }
        ss += v[p].x * v[p].x + v[p].y * v[p].y + v[p].z * v[p].z + v[p].w * v[p].w;
    }
#pragma unroll
    for (int off = 16; off; off >>= 1) ss += __shfl_xor_sync(~0u, ss, off);
    if ((tid & 31) == 0) red[tid >> 5] = ss;
    __syncthreads();
    if (tid == 0) {
        float t = 0.f;
#pragma unroll
        for (int i = 0; i < 8; ++i) t += red[i];
        red[0] = rsqrtf(t / (float)DIM + 1e-6f);
    }
    __syncthreads();
    float inv = red[0];
#pragma unroll
    for (int p = 0; p < 2; ++p) {
        int cix = p * 1024 + tid * 4;
        float4 wv = *(const float4*)(w + cix);
        __half2 h01 = f2h2(v[p].x * inv * wv.x, v[p].y * inv * wv.y);
        __half2 h23 = f2h2(v[p].z * inv * wv.z, v[p].w * inv * wv.w);
        *(uint2*)(out + (size_t)row * DIM + cix) =
            make_uint2(*(uint32_t*)&h01, *(uint32_t*)&h23);
    }
}

// ---------------- RoPE (in-place on q and k, f32) ---------------------------
__global__ void rope_kernel(float* __restrict__ q, float* __restrict__ k)
{
    int idx = blockIdx.x * blockDim.x + threadIdx.x;
    if (idx >= NROWS * NH * 64) return;
    int i   = idx & 63;
    int h   = (idx >> 6) & (NH - 1);
    int row = idx >> 10;
    int pos = row & (SQ - 1);
    float inv = (float)exp(-((double)(2 * i) / (double)HD) * 9.210340371976184);
    float ang = (float)pos * inv;
    float sn, cs;
    sincosf(ang, &sn, &cs);
    size_t base = (size_t)row * DIM + (size_t)h * HD;
    float a = q[base + i], b = q[base + i + 64];
    q[base + i]      = a * cs - b * sn;
    q[base + i + 64] = b * cs + a * sn;
    a = k[base + i]; b = k[base + i + 64];
    k[base + i]      = a * cs - b * sn;
    k[base + i + 64] = b * cs + a * sn;
}

// ---------------- Flash attention (causal, f32 math, half out) --------------
#define ATTN_SMEM_FLOATS (64*128 + 64*132 + 64*128 + 64*64)
#define ATTN_SMEM_BYTES  (ATTN_SMEM_FLOATS * 4)

__global__ __launch_bounds__(256) void attn_kernel(
    const float* __restrict__ Q, const float* __restrict__ K,
    const float* __restrict__ V, __half* __restrict__ O)
{
    extern __shared__ float smf[];
    float* Qs = smf;
    float* Ks = smf + 8192;
    float* Vs = smf + 8192 + 8448;
    float* Ps = smf + 8192 + 8448 + 8192;

    int qt = blockIdx.x, h = blockIdx.y, b = blockIdx.z;
    int tid = threadIdx.x;
    int ty = tid >> 4, tx = tid & 15;
    int qr0 = ty * 4;
    int dc0 = tx * 8;

    const float* Qb = Q + (size_t)b * SQ * DIM + (size_t)h * HD;
    const float* Kb = K + (size_t)b * SQ * DIM + (size_t)h * HD;
    const float* Vb = V + (size_t)b * SQ * DIM + (size_t)h * HD;

    for (int i = tid; i < 64 * 32; i += 256) {
        int r = i >> 5, cix = (i & 31) << 2;
        *(float4*)&Qs[r * 128 + cix] =
            *(const float4*)(Qb + (size_t)(qt * 64 + r) * DIM + cix);
    }

    float m[4], l[4], o[4][8];
#pragma unroll
    for (int i = 0; i < 4; ++i) {
        m[i] = -3.0e38f; l[i] = 0.f;
#pragma unroll
        for (int d = 0; d < 8; ++d) o[i][d] = 0.f;
    }
    __syncthreads();

    const float SCALE = 0.08838834764831845f;

    for (int kt = 0; kt <= qt; ++kt) {
        for (int i = tid; i < 64 * 32; i += 256) {
            int r = i >> 5, cix = (i & 31) << 2;
            *(float4*)&Ks[r * 132 + cix] =
                *(const float4*)(Kb + (size_t)(kt * 64 + r) * DIM + cix);
            *(float4*)&Vs[r * 128 + cix] =
                *(const float4*)(Vb + (size_t)(kt * 64 + r) * DIM + cix);
        }
        __syncthreads();

        float s[4][4];
#pragma unroll
        for (int i = 0; i < 4; ++i)
#pragma unroll
            for (int j = 0; j < 4; ++j) s[i][j] = 0.f;

        for (int d0 = 0; d0 < HD; d0 += 4) {
            float4 kf[4];
#pragma unroll
            for (int j = 0; j < 4; ++j)
                kf[j] = *(const float4*)&Ks[(tx + 16 * j) * 132 + d0];
#pragma unroll
            for (int i = 0; i < 4; ++i) {
                float4 qf = *(const float4*)&Qs[(qr0 + i) * 128 + d0];
#pragma unroll
                for (int j = 0; j < 4; ++j) {
                    s[i][j] = fmaf(qf.x, kf[j].x, s[i][j]);
                    s[i][j] = fmaf(qf.y, kf[j].y, s[i][j]);
                    s[i][j] = fmaf(qf.z, kf[j].z, s[i][j]);
                    s[i][j] = fmaf(qf.w, kf[j].w, s[i][j]);
                }
            }
        }

#pragma unroll
        for (int i = 0; i < 4; ++i)
#pragma unroll
            for (int j = 0; j < 4; ++j) s[i][j] *= SCALE;

        if (kt == qt) {
#pragma unroll
            for (int i = 0; i < 4; ++i) {
                int qidx = qt * 64 + qr0 + i;
#pragma unroll
                for (int j = 0; j < 4; ++j) {
                    int kidx = kt * 64 + tx + 16 * j;
                    if (kidx > qidx) s[i][j] = -1e30f;
                }
            }
        }

#pragma unroll
        for (int i = 0; i < 4; ++i) {
            float mr = fmaxf(fmaxf(s[i][0], s[i][1]), fmaxf(s[i][2], s[i][3]));
#pragma unroll
            for (int off = 1; off < 16; off <<= 1)
                mr = fmaxf(mr, __shfl_xor_sync(~0u, mr, off));
            float mn = fmaxf(m[i], mr);
            float corr = __expf(m[i] - mn);
            m[i] = mn;
            float p0 = __expf(s[i][0] - mn);
            float p1 = __expf(s[i][1] - mn);
            float p2 = __expf(s[i][2] - mn);
            float p3 = __expf(s[i][3] - mn);
            float ls = p0 + p1 + p2 + p3;
#pragma unroll
            for (int off = 1; off < 16; off <<= 1)
                ls += __shfl_xor_sync(~0u, ls, off);
            l[i] = l[i] * corr + ls;
#pragma unroll
            for (int d = 0; d < 8; ++d) o[i][d] *= corr;
            Ps[(qr0 + i) * 64 + tx]      = p0;
            Ps[(qr0 + i) * 64 + tx + 16] = p1;
            Ps[(qr0 + i) * 64 + tx + 32] = p2;
            Ps[(qr0 + i) * 64 + tx + 48] = p3;
        }
        __syncthreads();

        for (int kk = 0; kk < 64; ++kk) {
            float4 v0 = *(const float4*)&Vs[kk * 128 + dc0];
            float4 v1 = *(const float4*)&Vs[kk * 128 + dc0 + 4];
#pragma unroll
            for (int i = 0; i < 4; ++i) {
                float p = Ps[(qr0 + i) * 64 + kk];
                o[i][0] = fmaf(p, v0.x, o[i][0]);
                o[i][1] = fmaf(p, v0.y, o[i][1]);
                o[i][2] = fmaf(p, v0.z, o[i][2]);
                o[i][3] = fmaf(p, v0.w, o[i][3]);
                o[i][4] = fmaf(p, v1.x, o[i][4]);
                o[i][5] = fmaf(p, v1.y, o[i][5]);
                o[i][6] = fmaf(p, v1.z, o[i][6]);
                o[i][7] = fmaf(p, v1.w, o[i][7]);
            }
        }
        __syncthreads();
    }

    // half output (feeds Wo GEMM)
#pragma unroll
    for (int i = 0; i < 4; ++i) {
        float inv = 1.f / l[i];
        int row = qt * 64 + qr0 + i;
        __half* op = O + (size_t)(b * SQ + row) * DIM + (size_t)h * HD + dc0;
        __half2 h0 = f2h2(o[i][0] * inv, o[i][1] * inv);
        __half2 h1 = f2h2(o[i][2] * inv, o[i][3] * inv);
        __half2 h2 = f2h2(o[i][4] * inv, o[i][5] * inv);
        __half2 h3 = f2h2(o[i][6] * inv, o[i][7] * inv);
        *(uint4*)op = make_uint4(*(uint32_t*)&h0, *(uint32_t*)&h1,
                                 *(uint32_t*)&h2, *(uint32_t*)&h3);
    }
}

// ---------------- elementwise ----------------------------------------------
__global__ void silu_mul_kernel(const float* __restrict__ gte, const float* __restrict__ up,
                                __half* __restrict__ gg, int n)
{
    int i = blockIdx.x * blockDim.x + threadIdx.x;
    if (i < n) {
        float x = gte[i];
        float sig = 1.f / (1.f + expf(-x));
        gg[i] = __float2half_rn(x * sig * up[i]);
    }
}

// ---------------- launch ----------------------------------------------------
extern "C" void kernel_launch(void* const* d_in, const int* in_sizes, int n_in,
                              void* d_out, int out_size)
{
    const float* x       = (const float*)d_in[0];
    const float* w_in    = (const float*)d_in[1];
    const float* w_lcaN  = (const float*)d_in[2];
    const float* w_post  = (const float*)d_in[3];
    const float* Wq      = (const float*)d_in[4];
    const float* Wk      = (const float*)d_in[5];
    const float* Wv      = (const float*)d_in[6];
    const float* Wo      = (const float*)d_in[7];
    const float* W_lca   = (const float*)d_in[8];
    const float* W_gate  = (const float*)d_in[9];
    const float* W_up    = (const float*)d_in[10];
    const float* W_down  = (const float*)d_in[11];
    float* out = (float*)d_out;

    float *q, *k, *v, *ao, *h, *b, *u, *gate, *up, *diag;
    __half *hn, *at, *a, *t1, *gg;
    __half *wqkvT, *woT, *wlT, *wl, *wguT, *wdT;
    cudaGetSymbolAddress((void**)&q,    g_q);
    cudaGetSymbolAddress((void**)&k,    g_k);
    cudaGetSymbolAddress((void**)&v,    g_v);
    cudaGetSymbolAddress((void**)&ao,   g_ao);
    cudaGetSymbolAddress((void**)&h,    g_h);
    cudaGetSymbolAddress((void**)&b,    g_b);
    cudaGetSymbolAddress((void**)&u,    g_u);
    cudaGetSymbolAddress((void**)&gate, g_gate);
    cudaGetSymbolAddress((void**)&up,   g_up);
    cudaGetSymbolAddress((void**)&diag, g_diag);
    cudaGetSymbolAddress((void**)&hn,   g_hn);
    cudaGetSymbolAddress((void**)&at,   g_at);
    cudaGetSymbolAddress((void**)&a,    g_a);
    cudaGetSymbolAddress((void**)&t1,   g_t1);
    cudaGetSymbolAddress((void**)&gg,   g_gg);
    cudaGetSymbolAddress((void**)&wqkvT, g_wqkvT);
    cudaGetSymbolAddress((void**)&woT,   g_woT);
    cudaGetSymbolAddress((void**)&wlT,   g_wlT);
    cudaGetSymbolAddress((void**)&wl,    g_wl);
    cudaGetSymbolAddress((void**)&wguT,  g_wguT);
    cudaGetSymbolAddress((void**)&wdT,   g_wdT);

    cudaFuncSetAttribute(attn_kernel,
                         cudaFuncAttributeMaxDynamicSharedMemorySize, ATTN_SMEM_BYTES);
    cudaFuncSetAttribute(gemm_f16<0>,
                         cudaFuncAttributeMaxDynamicSharedMemorySize, GEMM_SMEM_BYTES);
    cudaFuncSetAttribute(gemm_f16<1>,
                         cudaFuncAttributeMaxDynamicSharedMemorySize, GEMM_SMEM_BYTES);
    cudaFuncSetAttribute(gemm_f16<2>,
                         cudaFuncAttributeMaxDynamicSharedMemorySize, GEMM_SMEM_BYTES);
    cudaFuncSetAttribute(gemm_f16<3>,
                         cudaFuncAttributeMaxDynamicSharedMemorySize, GEMM_SMEM_BYTES);
    cudaFuncSetAttribute(gemm_f16<4>,
                         cudaFuncAttributeMaxDynamicSharedMemorySize, GEMM_SMEM_BYTES);
    cudaFuncSetAttribute(gemm_f16<5>,
                         cudaFuncAttributeMaxDynamicSharedMemorySize, GEMM_SMEM_BYTES);
    cudaFuncSetAttribute(gemm_f16<6>,
                         cudaFuncAttributeMaxDynamicSharedMemorySize, GEMM_SMEM_BYTES);

    const int NF = NROWS * DFF;
    dim3 tp(32, 8);

    // ---- weight prep: transpose + half (K-major [N][K]) ----
    transpose_half_kernel<<<dim3(DIM/32,  DIM/32), tp>>>(Wq, wqkvT,                      DIM, DIM);
    transpose_half_kernel<<<dim3(DIM/32,  DIM/32), tp>>>(Wk, wqkvT + (size_t)DIM*DIM,    DIM, DIM);
    transpose_half_kernel<<<dim3(DIM/32,  DIM/32), tp>>>(Wv, wqkvT + (size_t)2*DIM*DIM,  DIM, DIM);
    transpose_half_kernel<<<dim3(DIM/32,  DIM/32), tp>>>(Wo, woT, DIM, DIM);
    transpose_half_kernel<<<dim3(DLCA/32, DIM/32), tp>>>(W_lca, wlT, DIM, DLCA);
    round_half_kernel<<<(DIM*DLCA + 255)/256, 256>>>(W_lca, wl, DIM*DLCA);
    transpose_half_kernel<<<dim3(DFF/32,  DIM/32), tp>>>(W_gate, wguT,                   DIM, DFF);
    transpose_half_kernel<<<dim3(DFF/32,  DIM/32), tp>>>(W_up,   wguT + (size_t)DFF*DIM, DIM, DFF);
    transpose_half_kernel<<<dim3(DIM/32,  DFF/32), tp>>>(W_down, wdT, DFF, DIM);
    diagG_kernel<<<DLCA / 256, 256>>>(wl, diag);

    dim3 gQKV(3*DIM / 128, NROWS / 128);
    dim3 gD  (DIM / 128,   NROWS / 128);
    dim3 gL  (DLCA / 128,  NROWS / 128);
    dim3 gGU (2*DFF / 128, NROWS / 128);

    // ---- attention block ----
    rmsnorm_kernel<<<NROWS, 256>>>(x, nullptr, nullptr, w_in, hn);
    gemm_f16<5><<<gQKV, 128, GEMM_SMEM_BYTES>>>(hn, wqkvT, q, k, v, nullptr, nullptr,
                                                3*DIM, DIM);
    rope_kernel<<<(NROWS * NH * 64 + 255) / 256, 256>>>(q, k);
    attn_kernel<<<dim3(SQ / 64, NH, BATCH), 256, ATTN_SMEM_BYTES>>>(q, k, v, at);
    gemm_f16<0><<<gD, 128, GEMM_SMEM_BYTES>>>(at, woT, ao, nullptr, nullptr, nullptr,
                                              nullptr, DIM, DIM);

    // ---- LCA block ----
    rmsnorm_kernel<<<NROWS, 256>>>(x, ao, h, w_lcaN, hn);
    gemm_f16<2><<<gL, 128, GEMM_SMEM_BYTES>>>(hn, wlT, b, u, nullptr, a, nullptr,
                                              DLCA, DIM);
    for (int it = 0; it < 9; ++it) {
        gemm_f16<1><<<gD, 128, GEMM_SMEM_BYTES>>>(a, wl, nullptr, nullptr, nullptr, t1,
                                                  nullptr, DIM, DLCA);
        gemm_f16<3><<<gL, 128, GEMM_SMEM_BYTES>>>(t1, wlT, nullptr, b, u, a, diag,
                                                  DLCA, DIM);
    }
    gemm_f16<0><<<gD, 128, GEMM_SMEM_BYTES>>>(a, wl, h, nullptr, nullptr, nullptr,
                                              nullptr, DIM, DLCA);

    // ---- MLP block ----
    rmsnorm_kernel<<<NROWS, 256>>>(h, nullptr, nullptr, w_post, hn);
    gemm_f16<6><<<gGU, 128, GEMM_SMEM_BYTES>>>(hn, wguT, gate, up, nullptr, nullptr,
                                               nullptr, 2*DFF, DIM);
    silu_mul_kernel<<<(NF + 255) / 256, 256>>>(gate, up, gg, NF);
    gemm_f16<4><<<gD, 128, GEMM_SMEM_BYTES>>>(gg, wdT, out, h, nullptr, nullptr,
                                              nullptr, DIM, DFF);
}

// round 13
// speedup vs baseline: 3.1750x; 1.1727x over previous
#include <cuda_runtime.h>
#include <cuda_fp16.h>
#include <math.h>
#include <stdint.h>

#define SQ    2048
#define DIM   2048
#define NH    16
#define HD    128
#define BATCH 2
#define NROWS 4096      // B*S
#define DLCA  4096
#define DFF   8192

// ---------------- scratch (static device globals; no allocs allowed) -------
__device__ float g_q   [(size_t)NROWS*DIM];
__device__ float g_k   [(size_t)NROWS*DIM];
__device__ float g_v   [(size_t)NROWS*DIM];
__device__ float g_ao  [(size_t)NROWS*DIM];
__device__ float g_h   [(size_t)NROWS*DIM];
__device__ float g_b   [(size_t)NROWS*DLCA];
__device__ float g_u   [(size_t)NROWS*DLCA];
__device__ float g_gate[(size_t)NROWS*DFF];
__device__ float g_up  [(size_t)NROWS*DFF];
__device__ float g_diag[DLCA];
// half activation buffers (GEMM A operands)
__device__ __half g_hn [(size_t)NROWS*DIM];
__device__ __half g_at [(size_t)NROWS*DIM];
__device__ __half g_a  [(size_t)NROWS*DLCA];
__device__ __half g_t1 [(size_t)NROWS*DIM];
__device__ __half g_gg [(size_t)NROWS*DFF];
// half weights, K-major [N][K]
__device__ __half g_wqkvT[(size_t)(3*DIM)*DIM];
__device__ __half g_woT  [(size_t)DIM*DIM];
__device__ __half g_wlT  [(size_t)DLCA*DIM];
__device__ __half g_wl   [(size_t)DIM*DLCA];
__device__ __half g_wguT [(size_t)(2*DFF)*DIM];
__device__ __half g_wdT  [(size_t)DIM*DFF];

// ---------------- helpers ----------------------------------------------------
__device__ __forceinline__ __half2 f2h2(float a, float b) {
    return __floats2half2_rn(a, b);
}
__device__ __forceinline__ uint32_t f2h2u(float a, float b) {
    __half2 t = __floats2half2_rn(a, b);
    return *(uint32_t*)&t;
}

#define CP_ASYNC16(dst, src) \
    asm volatile("cp.async.cg.shared.global [%0], [%1], 16;\n" :: "r"(dst), "l"(src))
#define CP_COMMIT() asm volatile("cp.async.commit_group;\n")
#define CP_WAIT1()  asm volatile("cp.async.wait_group 1;\n" ::: "memory")

#define MMA_F16(c, a0, a1, a2, a3, b0, b1) \
    asm volatile("mma.sync.aligned.m16n8k16.row.col.f32.f16.f16.f32 " \
                 "{%0,%1,%2,%3}, {%4,%5,%6,%7}, {%8,%9}, {%0,%1,%2,%3};" \
                 : "+f"((c)[0]), "+f"((c)[1]), "+f"((c)[2]), "+f"((c)[3]) \
                 : "r"(a0), "r"(a1), "r"(a2), "r"(a3), "r"(b0), "r"(b1))

#define LDSM4(r0, r1, r2, r3, adr) \
    asm volatile("ldmatrix.sync.aligned.m8n8.x4.shared.b16 {%0,%1,%2,%3}, [%4];" \
                 : "=r"(r0), "=r"(r1), "=r"(r2), "=r"(r3) : "r"(adr))

#define LDSM4T(r0, r1, r2, r3, adr) \
    asm volatile("ldmatrix.sync.aligned.m8n8.x4.trans.shared.b16 {%0,%1,%2,%3}, [%4];" \
                 : "=r"(r0), "=r"(r1), "=r"(r2), "=r"(r3) : "r"(adr))

// ================= FP16 GEMM (ldmatrix + fused epilogues) ===================
#define HSTRIDE 40
#define HFL (128 * HSTRIDE)
#define HSTG (2 * HFL)
#define GEMM_SMEM_BYTES (3 * HSTG * 2)

template<int MODE>
__global__ __launch_bounds__(128, 2) void gemm_f16(
    const __half* __restrict__ A, const __half* __restrict__ B,
    float* __restrict__ C, float* __restrict__ p0, float* __restrict__ p1,
    __half* __restrict__ hO, const float* __restrict__ dg,
    int N, int K)
{
    extern __shared__ __half smh[];
    const int tid  = threadIdx.x;
    const int warp = tid >> 5, lane = tid & 31;
    const int wm = warp & 1, wn = warp >> 1;
    const int g = lane >> 2, q = lane & 3;
    const int bx = blockIdx.x, by = blockIdx.y;

    const size_t ar0 = (size_t)by * 128;
    const size_t br0 = (size_t)bx * 128;
    unsigned smB = (unsigned)__cvta_generic_to_shared(smh);

    const int aRow = wm * 64 + (lane & 15);
    const int aK8  = 8 * (lane >> 4);
    const int bRow = wn * 64 + ((lane >> 4) << 3) + (lane & 7);
    const int bK8  = 8 * ((lane >> 3) & 1);

    float c[4][8][4];
#pragma unroll
    for (int i = 0; i < 4; ++i)
#pragma unroll
        for (int j = 0; j < 8; ++j)
#pragma unroll
            for (int r = 0; r < 4; ++r) c[i][j][r] = 0.f;

    const int T = K >> 5;

    auto load_stage = [&](int t, int s) {
        unsigned base = smB + (unsigned)(s * HSTG) * 2;
        const __half* Ap = A + ar0 * K + (size_t)t * 32;
        const __half* Bp = B + br0 * K + (size_t)t * 32;
#pragma unroll
        for (int i = 0; i < 4; ++i) {
            int u = tid + i * 128;
            int row = u >> 2, cc = (u & 3) << 3;
            CP_ASYNC16(base + (unsigned)(row * HSTRIDE + cc) * 2,
                       Ap + (size_t)row * K + cc);
            CP_ASYNC16(base + (unsigned)(HFL + row * HSTRIDE + cc) * 2,
                       Bp + (size_t)row * K + cc);
        }
    };

    load_stage(0, 0); CP_COMMIT();
    if (T > 1) load_stage(1, 1);
    CP_COMMIT();

    for (int t = 0; t < T; ++t) {
        CP_WAIT1();
        __syncthreads();
        if (t + 2 < T) load_stage(t + 2, (t + 2) % 3);
        CP_COMMIT();

        unsigned stB = smB + (unsigned)((t % 3) * HSTG) * 2;

#pragma unroll
        for (int k16 = 0; k16 < 2; ++k16) {
            const int ks = k16 * 16;
            uint32_t a[4][4], b[4][4];
#pragma unroll
            for (int mi = 0; mi < 4; ++mi) {
                unsigned adr = stB +
                    (unsigned)(((aRow + mi * 16) * HSTRIDE) + ks + aK8) * 2;
                LDSM4(a[mi][0], a[mi][1], a[mi][2], a[mi][3], adr);
            }
#pragma unroll
            for (int nj = 0; nj < 4; ++nj) {
                unsigned adr = stB + (unsigned)(HFL * 2) +
                    (unsigned)(((bRow + nj * 16) * HSTRIDE) + ks + bK8) * 2;
                LDSM4(b[nj][0], b[nj][1], b[nj][2], b[nj][3], adr);
            }
#pragma unroll
            for (int mi = 0; mi < 4; ++mi)
#pragma unroll
                for (int nj = 0; nj < 4; ++nj) {
                    MMA_F16(c[mi][2 * nj],
                            a[mi][0], a[mi][1], a[mi][2], a[mi][3],
                            b[nj][0], b[nj][1]);
                    MMA_F16(c[mi][2 * nj + 1],
                            a[mi][0], a[mi][1], a[mi][2], a[mi][3],
                            b[nj][2], b[nj][3]);
                }
        }
    }

    float* Cout = C;
    int Nout = N, colsub = 0;
    if constexpr (MODE == 5) {
        int which = (int)(br0 >> 11);
        Cout = (which == 0) ? C : (which == 1 ? p0 : p1);
        Nout = 2048; colsub = which * 2048;
    }
    if constexpr (MODE == 6) {
        int which = (int)(br0 >> 13);
        Cout = which ? p0 : C;
        Nout = 8192; colsub = which * 8192;
    }

#pragma unroll
    for (int mi = 0; mi < 4; ++mi) {
        int row0 = (int)ar0 + wm * 64 + mi * 16 + g;
#pragma unroll
        for (int ni = 0; ni < 8; ++ni) {
            int col = (int)br0 + wn * 64 + ni * 8 + q * 2;
#pragma unroll
            for (int hh = 0; hh < 2; ++hh) {
                int r = row0 + hh * 8;
                float v0 = c[mi][ni][hh * 2 + 0];
                float v1 = c[mi][ni][hh * 2 + 1];
                if constexpr (MODE == 0) {
                    *(float2*)(C + (size_t)r * N + col) = make_float2(v0, v1);
                } else if constexpr (MODE == 1) {
                    *(__half2*)(hO + (size_t)r * N + col) = f2h2(v0, v1);
                } else if constexpr (MODE == 2) {
                    size_t i0 = (size_t)r * N + col;
                    *(float2*)(C + i0) = make_float2(v0, v1);
                    float u0 = 0.1f * v0, u1 = 0.1f * v1;
                    *(float2*)(p0 + i0) = make_float2(u0, u1);
                    *(__half2*)(hO + i0) = f2h2(fmaxf(u0 - 0.1f, 0.f),
                                                fmaxf(u1 - 0.1f, 0.f));
                } else if constexpr (MODE == 3) {
                    size_t i0 = (size_t)r * N + col;
                    float2 dgv = *(const float2*)(dg + col);
                    __half2 ah = *(const __half2*)(hO + i0);
                    float2 av = __half22float2(ah);
                    float2 bb = *(const float2*)(p0 + i0);
                    float2 uv = *(const float2*)(p1 + i0);
                    float inh0 = v0 - av.x * dgv.x;
                    float inh1 = v1 - av.y * dgv.y;
                    uv.x += 0.1f * (bb.x - inh0 - uv.x);
                    uv.y += 0.1f * (bb.y - inh1 - uv.y);
                    *(float2*)(p1 + i0) = uv;
                    *(__half2*)(hO + i0) = f2h2(fmaxf(uv.x - 0.1f, 0.f),
                                                fmaxf(uv.y - 0.1f, 0.f));
                } else if constexpr (MODE == 4) {
                    size_t i0 = (size_t)r * N + col;
                    float2 rv = *(const float2*)(p0 + i0);
                    *(float2*)(C + i0) = make_float2(v0 + rv.x, v1 + rv.y);
                } else {
                    *(float2*)(Cout + (size_t)r * Nout + (col - colsub)) =
                        make_float2(v0, v1);
                }
            }
        }
    }
}

// ---------------- weight prep ----------------------------------------------
__global__ void transpose_half_kernel(const float* __restrict__ W,
                                      __half* __restrict__ To, int K, int N)
{
    __shared__ float tsm[32][33];
    int n0 = blockIdx.x * 32, k0 = blockIdx.y * 32;
    int tx = threadIdx.x, ty = threadIdx.y;
#pragma unroll
    for (int i = 0; i < 4; ++i)
        tsm[ty + i * 8][tx] = W[(size_t)(k0 + ty + i * 8) * N + n0 + tx];
    __syncthreads();
#pragma unroll
    for (int i = 0; i < 4; ++i) {
        int n = n0 + ty + i * 8;
        To[(size_t)n * K + k0 + tx] = __float2half_rn(tsm[tx][ty + i * 8]);
    }
}

__global__ void round_half_kernel(const float* __restrict__ s, __half* __restrict__ d, int n)
{
    int i = blockIdx.x * blockDim.x + threadIdx.x;
    if (i < n) d[i] = __float2half_rn(s[i]);
}

__global__ void diagG_kernel(const __half* __restrict__ Wh, float* __restrict__ diag)
{
    int j = blockIdx.x * blockDim.x + threadIdx.x;
    if (j < DLCA) {
        float s = 0.f;
        for (int i = 0; i < DIM; ++i) {
            float w = __half2float(Wh[(size_t)i * DLCA + j]);
            s = fmaf(w, w, s);
        }
        diag[j] = s;
    }
}

// ---------------- RMSNorm (emits half) --------------------------------------
__global__ __launch_bounds__(256) void rmsnorm_kernel(
    const float* __restrict__ x, const float* __restrict__ res,
    float* __restrict__ hsum, const float* __restrict__ w, __half* __restrict__ out)
{
    __shared__ float red[8];
    int row = blockIdx.x, tid = threadIdx.x;
    const float* xr = x + (size_t)row * DIM;
    float4 v[2];
    float ss = 0.f;
#pragma unroll
    for (int p = 0; p < 2; ++p) {
        int cix = p * 1024 + tid * 4;
        v[p] = *(const float4*)(xr + cix);
        if (res) {
            float4 rv = *(const float4*)(res + (size_t)row * DIM + cix);
            v[p].x += rv.x; v[p].y += rv.y; v[p].z += rv.z; v[p].w += rv.w;
            *(float4*)(hsum + (size_t)row * DIM + cix) = v[p];
        }
        ss += v[p].x * v[p].x + v[p].y * v[p].y + v[p].z * v[p].z + v[p].w * v[p].w;
    }
#pragma unroll
    for (int off = 16; off; off >>= 1) ss += __shfl_xor_sync(~0u, ss, off);
    if ((tid & 31) == 0) red[tid >> 5] = ss;
    __syncthreads();
    if (tid == 0) {
        float t = 0.f;
#pragma unroll
        for (int i = 0; i < 8; ++i) t += red[i];
        red[0] = rsqrtf(t / (float)DIM + 1e-6f);
    }
    __syncthreads();
    float inv = red[0];
#pragma unroll
    for (int p = 0; p < 2; ++p) {
        int cix = p * 1024 + tid * 4;
        float4 wv = *(const float4*)(w + cix);
        __half2 h01 = f2h2(v[p].x * inv * wv.x, v[p].y * inv * wv.y);
        __half2 h23 = f2h2(v[p].z * inv * wv.z, v[p].w * inv * wv.w);
        *(uint2*)(out + (size_t)row * DIM + cix) =
            make_uint2(*(uint32_t*)&h01, *(uint32_t*)&h23);
    }
}

// ---------------- RoPE (in-place on q and k, f32) ---------------------------
__global__ void rope_kernel(float* __restrict__ q, float* __restrict__ k)
{
    int idx = blockIdx.x * blockDim.x + threadIdx.x;
    if (idx >= NROWS * NH * 64) return;
    int i   = idx & 63;
    int h   = (idx >> 6) & (NH - 1);
    int row = idx >> 10;
    int pos = row & (SQ - 1);
    float inv = (float)exp(-((double)(2 * i) / (double)HD) * 9.210340371976184);
    float ang = (float)pos * inv;
    float sn, cs;
    sincosf(ang, &sn, &cs);
    size_t base = (size_t)row * DIM + (size_t)h * HD;
    float a = q[base + i], b = q[base + i + 64];
    q[base + i]      = a * cs - b * sn;
    q[base + i + 64] = b * cs + a * sn;
    a = k[base + i]; b = k[base + i + 64];
    k[base + i]      = a * cs - b * sn;
    k[base + i + 64] = b * cs + a * sn;
}

// ---------------- FP16 MMA flash attention (causal) -------------------------
// Block: 64 q-rows x (head, batch); 4 warps, each owns m16 of queries.
// S = Q K^T via m16n8k16 (fp32 accum), online softmax in registers,
// P repacked in-register to A-frags, O += P V via ldmatrix.trans B-frags.
#define AT_STRIDE 136
#define ATTN_SMEM_BYTES (3 * 64 * AT_STRIDE * 2)   // 52224

__global__ __launch_bounds__(128) void attn_f16(
    const float* __restrict__ Q, const float* __restrict__ K,
    const float* __restrict__ V, __half* __restrict__ O)
{
    extern __shared__ __half sma[];
    __half* Qs = sma;
    __half* Ks = sma + 64 * AT_STRIDE;
    __half* Vs = sma + 2 * 64 * AT_STRIDE;

    const int qt = blockIdx.x, h = blockIdx.y, b = blockIdx.z;
    const int tid = threadIdx.x, w = tid >> 5, lane = tid & 31;
    const int g = lane >> 2, q4 = lane & 3;

    const float* Qb = Q + (size_t)b * SQ * DIM + (size_t)h * HD;
    const float* Kb = K + (size_t)b * SQ * DIM + (size_t)h * HD;
    const float* Vb = V + (size_t)b * SQ * DIM + (size_t)h * HD;

    unsigned QsB = (unsigned)__cvta_generic_to_shared(Qs);
    unsigned KsB = (unsigned)__cvta_generic_to_shared(Ks);
    unsigned VsB = (unsigned)__cvta_generic_to_shared(Vs);

    // stage Q (f32 -> half)
    for (int i = tid; i < 64 * 16; i += 128) {
        int r = i >> 4, cix = (i & 15) * 8;
        const float* src = Qb + (size_t)(qt * 64 + r) * DIM + cix;
        float4 f0 = *(const float4*)src;
        float4 f1 = *(const float4*)(src + 4);
        *(uint4*)(Qs + r * AT_STRIDE + cix) =
            make_uint4(f2h2u(f0.x, f0.y), f2h2u(f0.z, f0.w),
                       f2h2u(f1.x, f1.y), f2h2u(f1.z, f1.w));
    }

    float o[16][4];
#pragma unroll
    for (int j = 0; j < 16; ++j)
#pragma unroll
        for (int r = 0; r < 4; ++r) o[j][r] = 0.f;
    float m0 = -1e30f, m1 = -1e30f, l0 = 0.f, l1 = 0.f;

    const int aRow = w * 16 + (lane & 15);
    const int aK8  = 8 * (lane >> 4);
    const int bR   = ((lane >> 4) << 3) + (lane & 7);
    const int bK8  = 8 * ((lane >> 3) & 1);
    const int vKey = ((lane >> 3) & 1) * 8 + (lane & 7);
    const int vD8  = (lane >> 4) * 8;

    const float SCALE = 0.08838834764831845f;
    const int qi0 = qt * 64 + w * 16 + g;
    const int qi1 = qi0 + 8;

    __syncthreads();

    for (int kt = 0; kt <= qt; ++kt) {
        // stage K, V (f32 -> half)
        for (int i = tid; i < 64 * 16; i += 128) {
            int r = i >> 4, cix = (i & 15) * 8;
            const float* sk = Kb + (size_t)(kt * 64 + r) * DIM + cix;
            const float* sv = Vb + (size_t)(kt * 64 + r) * DIM + cix;
            float4 f0 = *(const float4*)sk;
            float4 f1 = *(const float4*)(sk + 4);
            *(uint4*)(Ks + r * AT_STRIDE + cix) =
                make_uint4(f2h2u(f0.x, f0.y), f2h2u(f0.z, f0.w),
                           f2h2u(f1.x, f1.y), f2h2u(f1.z, f1.w));
            f0 = *(const float4*)sv;
            f1 = *(const float4*)(sv + 4);
            *(uint4*)(Vs + r * AT_STRIDE + cix) =
                make_uint4(f2h2u(f0.x, f0.y), f2h2u(f0.z, f0.w),
                           f2h2u(f1.x, f1.y), f2h2u(f1.z, f1.w));
        }
        __syncthreads();

        // ---- S = Q K^T (64x64 per block, m16 per warp) ----
        float s[8][4];
#pragma unroll
        for (int j = 0; j < 8; ++j)
#pragma unroll
            for (int r = 0; r < 4; ++r) s[j][r] = 0.f;

#pragma unroll
        for (int k16 = 0; k16 < 8; ++k16) {
            uint32_t a0, a1, a2, a3;
            LDSM4(a0, a1, a2, a3,
                  QsB + (unsigned)(aRow * AT_STRIDE + k16 * 16 + aK8) * 2);
#pragma unroll
            for (int nj2 = 0; nj2 < 4; ++nj2) {
                uint32_t r0, r1, r2, r3;
                LDSM4(r0, r1, r2, r3,
                      KsB + (unsigned)((nj2 * 16 + bR) * AT_STRIDE + k16 * 16 + bK8) * 2);
                MMA_F16(s[2 * nj2],     a0, a1, a2, a3, r0, r1);
                MMA_F16(s[2 * nj2 + 1], a0, a1, a2, a3, r2, r3);
            }
        }

        // scale + causal mask
#pragma unroll
        for (int j = 0; j < 8; ++j)
#pragma unroll
            for (int r = 0; r < 4; ++r) s[j][r] *= SCALE;
        if (kt == qt) {
#pragma unroll
            for (int j = 0; j < 8; ++j) {
                int k0 = kt * 64 + j * 8 + 2 * q4;
                if (k0     > qi0) s[j][0] = -1e30f;
                if (k0 + 1 > qi0) s[j][1] = -1e30f;
                if (k0     > qi1) s[j][2] = -1e30f;
                if (k0 + 1 > qi1) s[j][3] = -1e30f;
            }
        }

        // ---- online softmax (rows g and g+8) ----
        float mr0 = -1e30f, mr1 = -1e30f;
#pragma unroll
        for (int j = 0; j < 8; ++j) {
            mr0 = fmaxf(mr0, fmaxf(s[j][0], s[j][1]));
            mr1 = fmaxf(mr1, fmaxf(s[j][2], s[j][3]));
        }
        mr0 = fmaxf(mr0, __shfl_xor_sync(~0u, mr0, 1));
        mr0 = fmaxf(mr0, __shfl_xor_sync(~0u, mr0, 2));
        mr1 = fmaxf(mr1, __shfl_xor_sync(~0u, mr1, 1));
        mr1 = fmaxf(mr1, __shfl_xor_sync(~0u, mr1, 2));
        float mn0 = fmaxf(m0, mr0), mn1 = fmaxf(m1, mr1);
        float corr0 = __expf(m0 - mn0), corr1 = __expf(m1 - mn1);
        m0 = mn0; m1 = mn1;
        float ls0 = 0.f, ls1 = 0.f;
#pragma unroll
        for (int j = 0; j < 8; ++j) {
            s[j][0] = __expf(s[j][0] - mn0);
            s[j][1] = __expf(s[j][1] - mn0);
            s[j][2] = __expf(s[j][2] - mn1);
            s[j][3] = __expf(s[j][3] - mn1);
            ls0 += s[j][0] + s[j][1];
            ls1 += s[j][2] + s[j][3];
        }
        ls0 += __shfl_xor_sync(~0u, ls0, 1); ls0 += __shfl_xor_sync(~0u, ls0, 2);
        ls1 += __shfl_xor_sync(~0u, ls1, 1); ls1 += __shfl_xor_sync(~0u, ls1, 2);
        l0 = l0 * corr0 + ls0;
        l1 = l1 * corr1 + ls1;
#pragma unroll
        for (int j = 0; j < 16; ++j) {
            o[j][0] *= corr0; o[j][1] *= corr0;
            o[j][2] *= corr1; o[j][3] *= corr1;
        }

        // ---- O += P V (P in registers; V via ldmatrix.trans) ----
#pragma unroll
        for (int t = 0; t < 4; ++t) {
            uint32_t a0 = f2h2u(s[2 * t][0],     s[2 * t][1]);
            uint32_t a1 = f2h2u(s[2 * t][2],     s[2 * t][3]);
            uint32_t a2 = f2h2u(s[2 * t + 1][0], s[2 * t + 1][1]);
            uint32_t a3 = f2h2u(s[2 * t + 1][2], s[2 * t + 1][3]);
#pragma unroll
            for (int d16 = 0; d16 < 8; ++d16) {
                uint32_t r0, r1, r2, r3;
                LDSM4T(r0, r1, r2, r3,
                       VsB + (unsigned)((t * 16 + vKey) * AT_STRIDE + d16 * 16 + vD8) * 2);
                MMA_F16(o[2 * d16],     a0, a1, a2, a3, r0, r1);
                MMA_F16(o[2 * d16 + 1], a0, a1, a2, a3, r2, r3);
            }
        }
        __syncthreads();
    }

    // ---- write O (half, feeds Wo GEMM) ----
    float inv0 = 1.f / l0, inv1 = 1.f / l1;
    __half* Ob = O + (size_t)(b * SQ) * DIM + (size_t)h * HD;
#pragma unroll
    for (int j = 0; j < 16; ++j) {
        int col = j * 8 + 2 * q4;
        *(__half2*)(Ob + (size_t)qi0 * DIM + col) = f2h2(o[j][0] * inv0, o[j][1] * inv0);
        *(__half2*)(Ob + (size_t)qi1 * DIM + col) = f2h2(o[j][2] * inv1, o[j][3] * inv1);
    }
}

// ---------------- elementwise ----------------------------------------------
__global__ void silu_mul_kernel(const float* __restrict__ gte, const float* __restrict__ up,
                                __half* __restrict__ gg, int n)
{
    int i = blockIdx.x * blockDim.x + threadIdx.x;
    if (i < n) {
        float x = gte[i];
        float sig = 1.f / (1.f + expf(-x));
        gg[i] = __float2half_rn(x * sig * up[i]);
    }
}

// ---------------- launch ----------------------------------------------------
extern "C" void kernel_launch(void* const* d_in, const int* in_sizes, int n_in,
                              void* d_out, int out_size)
{
    const float* x       = (const float*)d_in[0];
    const float* w_in    = (const float*)d_in[1];
    const float* w_lcaN  = (const float*)d_in[2];
    const float* w_post  = (const float*)d_in[3];
    const float* Wq      = (const float*)d_in[4];
    const float* Wk      = (const float*)d_in[5];
    const float* Wv      = (const float*)d_in[6];
    const float* Wo      = (const float*)d_in[7];
    const float* W_lca   = (const float*)d_in[8];
    const float* W_gate  = (const float*)d_in[9];
    const float* W_up    = (const float*)d_in[10];
    const float* W_down  = (const float*)d_in[11];
    float* out = (float*)d_out;

    float *q, *k, *v, *ao, *h, *b, *u, *gate, *up, *diag;
    __half *hn, *at, *a, *t1, *gg;
    __half *wqkvT, *woT, *wlT, *wl, *wguT, *wdT;
    cudaGetSymbolAddress((void**)&q,    g_q);
    cudaGetSymbolAddress((void**)&k,    g_k);
    cudaGetSymbolAddress((void**)&v,    g_v);
    cudaGetSymbolAddress((void**)&ao,   g_ao);
    cudaGetSymbolAddress((void**)&h,    g_h);
    cudaGetSymbolAddress((void**)&b,    g_b);
    cudaGetSymbolAddress((void**)&u,    g_u);
    cudaGetSymbolAddress((void**)&gate, g_gate);
    cudaGetSymbolAddress((void**)&up,   g_up);
    cudaGetSymbolAddress((void**)&diag, g_diag);
    cudaGetSymbolAddress((void**)&hn,   g_hn);
    cudaGetSymbolAddress((void**)&at,   g_at);
    cudaGetSymbolAddress((void**)&a,    g_a);
    cudaGetSymbolAddress((void**)&t1,   g_t1);
    cudaGetSymbolAddress((void**)&gg,   g_gg);
    cudaGetSymbolAddress((void**)&wqkvT, g_wqkvT);
    cudaGetSymbolAddress((void**)&woT,   g_woT);
    cudaGetSymbolAddress((void**)&wlT,   g_wlT);
    cudaGetSymbolAddress((void**)&wl,    g_wl);
    cudaGetSymbolAddress((void**)&wguT,  g_wguT);
    cudaGetSymbolAddress((void**)&wdT,   g_wdT);

    cudaFuncSetAttribute(attn_f16,
                         cudaFuncAttributeMaxDynamicSharedMemorySize, ATTN_SMEM_BYTES);
    cudaFuncSetAttribute(gemm_f16<0>,
                         cudaFuncAttributeMaxDynamicSharedMemorySize, GEMM_SMEM_BYTES);
    cudaFuncSetAttribute(gemm_f16<1>,
                         cudaFuncAttributeMaxDynamicSharedMemorySize, GEMM_SMEM_BYTES);
    cudaFuncSetAttribute(gemm_f16<2>,
                         cudaFuncAttributeMaxDynamicSharedMemorySize, GEMM_SMEM_BYTES);
    cudaFuncSetAttribute(gemm_f16<3>,
                         cudaFuncAttributeMaxDynamicSharedMemorySize, GEMM_SMEM_BYTES);
    cudaFuncSetAttribute(gemm_f16<4>,
                         cudaFuncAttributeMaxDynamicSharedMemorySize, GEMM_SMEM_BYTES);
    cudaFuncSetAttribute(gemm_f16<5>,
                         cudaFuncAttributeMaxDynamicSharedMemorySize, GEMM_SMEM_BYTES);
    cudaFuncSetAttribute(gemm_f16<6>,
                         cudaFuncAttributeMaxDynamicSharedMemorySize, GEMM_SMEM_BYTES);

    const int NF = NROWS * DFF;
    dim3 tp(32, 8);

    // ---- weight prep ----
    transpose_half_kernel<<<dim3(DIM/32,  DIM/32), tp>>>(Wq, wqkvT,                      DIM, DIM);
    transpose_half_kernel<<<dim3(DIM/32,  DIM/32), tp>>>(Wk, wqkvT + (size_t)DIM*DIM,    DIM, DIM);
    transpose_half_kernel<<<dim3(DIM/32,  DIM/32), tp>>>(Wv, wqkvT + (size_t)2*DIM*DIM,  DIM, DIM);
    transpose_half_kernel<<<dim3(DIM/32,  DIM/32), tp>>>(Wo, woT, DIM, DIM);
    transpose_half_kernel<<<dim3(DLCA/32, DIM/32), tp>>>(W_lca, wlT, DIM, DLCA);
    round_half_kernel<<<(DIM*DLCA + 255)/256, 256>>>(W_lca, wl, DIM*DLCA);
    transpose_half_kernel<<<dim3(DFF/32,  DIM/32), tp>>>(W_gate, wguT,                   DIM, DFF);
    transpose_half_kernel<<<dim3(DFF/32,  DIM/32), tp>>>(W_up,   wguT + (size_t)DFF*DIM, DIM, DFF);
    transpose_half_kernel<<<dim3(DIM/32,  DFF/32), tp>>>(W_down, wdT, DFF, DIM);
    diagG_kernel<<<DLCA / 256, 256>>>(wl, diag);

    dim3 gQKV(3*DIM / 128, NROWS / 128);
    dim3 gD  (DIM / 128,   NROWS / 128);
    dim3 gL  (DLCA / 128,  NROWS / 128);
    dim3 gGU (2*DFF / 128, NROWS / 128);

    // ---- attention block ----
    rmsnorm_kernel<<<NROWS, 256>>>(x, nullptr, nullptr, w_in, hn);
    gemm_f16<5><<<gQKV, 128, GEMM_SMEM_BYTES>>>(hn, wqkvT, q, k, v, nullptr, nullptr,
                                                3*DIM, DIM);
    rope_kernel<<<(NROWS * NH * 64 + 255) / 256, 256>>>(q, k);
    attn_f16<<<dim3(SQ / 64, NH, BATCH), 128, ATTN_SMEM_BYTES>>>(q, k, v, at);
    gemm_f16<0><<<gD, 128, GEMM_SMEM_BYTES>>>(at, woT, ao, nullptr, nullptr, nullptr,
                                              nullptr, DIM, DIM);

    // ---- LCA block ----
    rmsnorm_kernel<<<NROWS, 256>>>(x, ao, h, w_lcaN, hn);
    gemm_f16<2><<<gL, 128, GEMM_SMEM_BYTES>>>(hn, wlT, b, u, nullptr, a, nullptr,
                                              DLCA, DIM);
    for (int it = 0; it < 9; ++it) {
        gemm_f16<1><<<gD, 128, GEMM_SMEM_BYTES>>>(a, wl, nullptr, nullptr, nullptr, t1,
                                                  nullptr, DIM, DLCA);
        gemm_f16<3><<<gL, 128, GEMM_SMEM_BYTES>>>(t1, wlT, nullptr, b, u, a, diag,
                                                  DLCA, DIM);
    }
    gemm_f16<0><<<gD, 128, GEMM_SMEM_BYTES>>>(a, wl, h, nullptr, nullptr, nullptr,
                                              nullptr, DIM, DLCA);

    // ---- MLP block ----
    rmsnorm_kernel<<<NROWS, 256>>>(h, nullptr, nullptr, w_post, hn);
    gemm_f16<6><<<gGU, 128, GEMM_SMEM_BYTES>>>(hn, wguT, gate, up, nullptr, nullptr,
                                               nullptr, 2*DFF, DIM);
    silu_mul_kernel<<<(NF + 255) / 256, 256>>>(gate, up, gg, NF);
    gemm_f16<4><<<gD, 128, GEMM_SMEM_BYTES>>>(gg, wdT, out, h, nullptr, nullptr,
                                              nullptr, DIM, DFF);
}